// round 5
// baseline (speedup 1.0000x reference)
#include <cuda_runtime.h>
#include <cuda_bf16.h>
#include <math.h>
#include <stdint.h>

#define NN 20000
#define NE 200000

// ---------------- scratch (device globals; allocation-free rule) ----------------
__device__ __align__(16) float g_h[NN*64];      // node features [N,64] (fp32, for final head)
__device__ __align__(16) float g_ni[NN*256];    // h @ Wni   [N,256]
__device__ __align__(16) float g_nj[NN*256];    // h @ Wnj   [N,256]
__device__ __align__(16) float g_hp[NN*256];    // h @ Wnode + bnode [N,256]
__device__ __align__(16) float g_score[NE*4];   // per-edge per-head scores
__device__ int g_rowptr[NN+1];
__device__ int g_cur[NN];
__device__ int g_eidx[NE];
// split-bf16 operands and converted weight images
__device__ __align__(16) __nv_bfloat16 g_hb[NN*128];     // [hi|lo] of h
__device__ __align__(16) __nv_bfloat16 g_fb[NE*128];     // [hi|lo] of f
__device__ __align__(16) __nv_bfloat16 g_wbuf[8*49152];  // 8 x [256 n][192 k] images

// ---------------- CSR build ----------------
__global__ void k_zero_cnt(){
    int i = blockIdx.x*blockDim.x + threadIdx.x;
    if (i < NN) g_cur[i] = 0;
}
__global__ void k_count(const int* __restrict__ dst){
    int e = blockIdx.x*blockDim.x + threadIdx.x;
    if (e < NE) atomicAdd(&g_cur[dst[e]], 1);
}
__global__ __launch_bounds__(1024) void k_scan(){
    __shared__ int sPart[1024];
    const int t = threadIdx.x;
    const int beg = t*20;
    const int end = (beg+20 < NN) ? beg+20 : NN;
    int s = 0;
    for (int i=beg; i<end; i++) s += g_cur[i];
    sPart[t] = s;
    __syncthreads();
    for (int o=1; o<1024; o<<=1){
        int v = (t >= o) ? sPart[t-o] : 0;
        __syncthreads();
        sPart[t] += v;
        __syncthreads();
    }
    int run = (t==0) ? 0 : sPart[t-1];
    for (int i=beg; i<end; i++){
        int c = g_cur[i];
        g_rowptr[i] = run;
        g_cur[i]    = run;
        run += c;
    }
    if (t == 0) g_rowptr[NN] = NE;
}
__global__ void k_scatter(const int* __restrict__ dst){
    int e = blockIdx.x*blockDim.x + threadIdx.x;
    if (e < NE){
        int p = atomicAdd(&g_cur[dst[e]], 1);
        g_eidx[p] = e;
    }
}

// ---------------- W' image [n][kk], kk<128 -> hi(W[kk&63][n]); else lo ----------------
__global__ __launch_bounds__(256) void k_wconv(const float* __restrict__ W, __nv_bfloat16* __restrict__ dst){
    int idx = blockIdx.x*256 + threadIdx.x;       // 49152
    if (idx >= 49152) return;
    int n = idx / 192, kk = idx % 192;
    int ks = kk & 63;
    float v = W[ks*256 + n];
    __nv_bfloat16 h = __float2bfloat16(v);
    if (kk >= 128) h = __float2bfloat16(v - __bfloat162float(h));
    dst[n*192 + kk] = h;
}

// ---------------- bf16 HMMA GEMM (nodes): out[rows,256] = split(A) @ W' ----------------
#define MSTR 200
#define MMA_SMEM (2*128*MSTR*2)

__global__ __launch_bounds__(256) void mma_gemm(
    const __nv_bfloat16* __restrict__ ab, const __nv_bfloat16* __restrict__ wimg0,
    const float* __restrict__ bias2,
    float* __restrict__ o0, float* __restrict__ o1, float* __restrict__ o2,
    int rows, int nmats){
    extern __shared__ __nv_bfloat16 sm[];
    __nv_bfloat16* sA = sm;
    __nv_bfloat16* sW = sm + 128*MSTR;
    const int tid = threadIdx.x;
    const int y = blockIdx.y;
    const int mat = (nmats == 3) ? (y >> 1) : 0;
    const int ch  = (nmats == 3) ? (y & 1)  : y;
    const __nv_bfloat16* wimg = wimg0 + (size_t)mat*49152;
    float* out = (mat==0) ? o0 : (mat==1) ? o1 : o2;
    const float* bias = (mat==2) ? bias2 : nullptr;
    const int row0 = blockIdx.x*128;
    const int cb   = ch*128;

    #pragma unroll
    for (int it=0; it<8; it++){
        int idx = it*256 + tid;
        int r = idx >> 4, c8 = (idx & 15)*8;
        uint4 v = make_uint4(0u,0u,0u,0u);
        if (row0 + r < rows) v = *reinterpret_cast<const uint4*>(ab + (size_t)(row0+r)*128 + c8);
        *reinterpret_cast<uint4*>(sA + r*MSTR + c8) = v;
    }
    #pragma unroll
    for (int it=0; it<4; it++){
        int idx = it*256 + tid;
        int r = idx >> 3, c8 = (idx & 7)*8;
        uint4 v = make_uint4(0u,0u,0u,0u);
        if (row0 + r < rows) v = *reinterpret_cast<const uint4*>(ab + (size_t)(row0+r)*128 + c8);
        *reinterpret_cast<uint4*>(sA + r*MSTR + 128 + c8) = v;
    }
    #pragma unroll
    for (int it=0; it<12; it++){
        int idx = it*256 + tid;
        int n = idx / 24, c8 = (idx % 24)*8;
        uint4 v = *reinterpret_cast<const uint4*>(wimg + (size_t)(cb+n)*192 + c8);
        *reinterpret_cast<uint4*>(sW + n*MSTR + c8) = v;
    }
    __syncthreads();

    const int wid = tid >> 5, lane = tid & 31;
    const int wrow = wid & 1, wcol = wid >> 1;
    const int lr = lane >> 2, lk2 = (lane & 3)*2;

    float acc[4][4][4];
    #pragma unroll
    for (int mi=0;mi<4;mi++)
        #pragma unroll
        for (int ni=0;ni<4;ni++)
            #pragma unroll
            for (int q=0;q<4;q++) acc[mi][ni][q] = 0.f;

    #pragma unroll
    for (int ks=0; ks<12; ks++){
        const int k = ks*16;
        uint32_t afr[4][4];
        #pragma unroll
        for (int mi=0;mi<4;mi++){
            const __nv_bfloat16* ap = sA + (wrow*64 + mi*16 + lr)*MSTR + k + lk2;
            afr[mi][0] = *reinterpret_cast<const uint32_t*>(ap);
            afr[mi][1] = *reinterpret_cast<const uint32_t*>(ap + 8*MSTR);
            afr[mi][2] = *reinterpret_cast<const uint32_t*>(ap + 8);
            afr[mi][3] = *reinterpret_cast<const uint32_t*>(ap + 8*MSTR + 8);
        }
        #pragma unroll
        for (int ni=0;ni<4;ni++){
            const __nv_bfloat16* bp = sW + (wcol*32 + ni*8 + lr)*MSTR + k + lk2;
            uint32_t b0 = *reinterpret_cast<const uint32_t*>(bp);
            uint32_t b1 = *reinterpret_cast<const uint32_t*>(bp + 8);
            #pragma unroll
            for (int mi=0;mi<4;mi++){
                asm volatile(
                    "mma.sync.aligned.m16n8k16.row.col.f32.bf16.bf16.f32 "
                    "{%0,%1,%2,%3}, {%4,%5,%6,%7}, {%8,%9}, {%0,%1,%2,%3};"
                    : "+f"(acc[mi][ni][0]), "+f"(acc[mi][ni][1]),
                      "+f"(acc[mi][ni][2]), "+f"(acc[mi][ni][3])
                    : "r"(afr[mi][0]), "r"(afr[mi][1]), "r"(afr[mi][2]), "r"(afr[mi][3]),
                      "r"(b0), "r"(b1));
            }
        }
    }

    #pragma unroll
    for (int mi=0;mi<4;mi++){
        #pragma unroll
        for (int ni=0;ni<4;ni++){
            int r = row0 + wrow*64 + mi*16 + lr;
            int c = cb + wcol*32 + ni*8 + lk2;
            float bx = 0.f, by = 0.f;
            if (bias){ bx = bias[c]; by = bias[c+1]; }
            if (r < rows){
                float2 v = make_float2(acc[mi][ni][0] + bx, acc[mi][ni][1] + by);
                *reinterpret_cast<float2*>(out + (size_t)r*256 + c) = v;
            }
            if (r + 8 < rows){
                float2 v = make_float2(acc[mi][ni][2] + bx, acc[mi][ni][3] + by);
                *reinterpret_cast<float2*>(out + (size_t)(r+8)*256 + c) = v;
            }
        }
    }
}

// ---------------- fused edge kernel: fij GEMM + edge update + scores + new f (split) ----------------
// CTA: 128 edges x 256 cols, 512 threads (16 warps, warp tile 32x64), K=192.
#define FW_STR 260
#define EF_SMEM (128*MSTR*2 + 256*MSTR*2)   // 153600; fw overlay 128*260*4=133120 fits

__global__ __launch_bounds__(512) void edge_fused(
    const __nv_bfloat16* __restrict__ wimg,    // fij image [256][192]
    const int* __restrict__ src, const int* __restrict__ dst,
    const float* __restrict__ bias_e, const float* __restrict__ attn){
    extern __shared__ __nv_bfloat16 sm[];
    __nv_bfloat16* sA = sm;              // [128][MSTR]
    __nv_bfloat16* sW = sm + 128*MSTR;   // [256][MSTR]
    float* fws = reinterpret_cast<float*>(sm);   // overlay after MMA: [128][FW_STR]
    const int tid = threadIdx.x;
    const int e0 = blockIdx.x*128;

    // stage 1: load A (128 edges split-bf16) and full W
    #pragma unroll
    for (int it=0; it<4; it++){
        int idx = it*512 + tid;                  // 2048
        int r = idx >> 4, c8 = (idx & 15)*8;
        uint4 v = make_uint4(0u,0u,0u,0u);
        if (e0 + r < NE) v = *reinterpret_cast<const uint4*>(g_fb + (size_t)(e0+r)*128 + c8);
        *reinterpret_cast<uint4*>(sA + r*MSTR + c8) = v;
    }
    #pragma unroll
    for (int it=0; it<2; it++){
        int idx = it*512 + tid;                  // 1024
        int r = idx >> 3, c8 = (idx & 7)*8;
        uint4 v = make_uint4(0u,0u,0u,0u);
        if (e0 + r < NE) v = *reinterpret_cast<const uint4*>(g_fb + (size_t)(e0+r)*128 + c8);
        *reinterpret_cast<uint4*>(sA + r*MSTR + 128 + c8) = v;
    }
    #pragma unroll
    for (int it=0; it<12; it++){
        int idx = it*512 + tid;                  // 6144
        int n = idx / 24, c8 = (idx % 24)*8;
        uint4 v = *reinterpret_cast<const uint4*>(wimg + (size_t)n*192 + c8);
        *reinterpret_cast<uint4*>(sW + n*MSTR + c8) = v;
    }
    __syncthreads();

    const int wid = tid >> 5, lane = tid & 31;
    const int wrow = wid & 3, wcol = wid >> 2;
    const int lr = lane >> 2, lk2 = (lane & 3)*2;

    float acc[2][8][4];
    #pragma unroll
    for (int mi=0;mi<2;mi++)
        #pragma unroll
        for (int ni=0;ni<8;ni++)
            #pragma unroll
            for (int q=0;q<4;q++) acc[mi][ni][q] = 0.f;

    #pragma unroll
    for (int ks=0; ks<12; ks++){
        const int k = ks*16;
        uint32_t afr[2][4];
        #pragma unroll
        for (int mi=0;mi<2;mi++){
            const __nv_bfloat16* ap = sA + (wrow*32 + mi*16 + lr)*MSTR + k + lk2;
            afr[mi][0] = *reinterpret_cast<const uint32_t*>(ap);
            afr[mi][1] = *reinterpret_cast<const uint32_t*>(ap + 8*MSTR);
            afr[mi][2] = *reinterpret_cast<const uint32_t*>(ap + 8);
            afr[mi][3] = *reinterpret_cast<const uint32_t*>(ap + 8*MSTR + 8);
        }
        #pragma unroll
        for (int ni=0;ni<8;ni++){
            const __nv_bfloat16* bp = sW + (wcol*64 + ni*8 + lr)*MSTR + k + lk2;
            uint32_t b0 = *reinterpret_cast<const uint32_t*>(bp);
            uint32_t b1 = *reinterpret_cast<const uint32_t*>(bp + 8);
            #pragma unroll
            for (int mi=0;mi<2;mi++){
                asm volatile(
                    "mma.sync.aligned.m16n8k16.row.col.f32.bf16.bf16.f32 "
                    "{%0,%1,%2,%3}, {%4,%5,%6,%7}, {%8,%9}, {%0,%1,%2,%3};"
                    : "+f"(acc[mi][ni][0]), "+f"(acc[mi][ni][1]),
                      "+f"(acc[mi][ni][2]), "+f"(acc[mi][ni][3])
                    : "r"(afr[mi][0]), "r"(afr[mi][1]), "r"(afr[mi][2]), "r"(afr[mi][3]),
                      "r"(b0), "r"(b1));
            }
        }
    }
    __syncthreads();   // done reading sA/sW

    // spill accumulators to smem fw [128][FW_STR]
    #pragma unroll
    for (int mi=0;mi<2;mi++){
        #pragma unroll
        for (int ni=0;ni<8;ni++){
            int r = wrow*32 + mi*16 + lr;
            int c = wcol*64 + ni*8 + lk2;
            *reinterpret_cast<float2*>(fws + r*FW_STR + c)       = make_float2(acc[mi][ni][0], acc[mi][ni][1]);
            *reinterpret_cast<float2*>(fws + (r+8)*FW_STR + c)   = make_float2(acc[mi][ni][2], acc[mi][ni][3]);
        }
    }
    __syncthreads();

    // stage 2: edge update. 8 groups of 64 threads; one edge per group per iteration.
    __shared__ float sRm[16], sRv[16];
    const int g = tid >> 6;
    const int t = tid & 63;
    const float4 be = reinterpret_cast<const float4*>(bias_e)[t];
    const float4 at = reinterpret_cast<const float4*>(attn)[t];

    #pragma unroll 1
    for (int it=0; it<16; it++){
        const int el = g + it*8;
        const int e  = e0 + el;
        const bool valid = (e < NE);
        float4 fo = *reinterpret_cast<const float4*>(fws + el*FW_STR + 4*t);
        fo.x += be.x; fo.y += be.y; fo.z += be.z; fo.w += be.w;
        if (valid){
            int s = src[e], d = dst[e];
            float4 ni4 = reinterpret_cast<const float4*>(g_ni)[s*64 + t];
            float4 nj4 = reinterpret_cast<const float4*>(g_nj)[d*64 + t];
            fo.x += ni4.x + nj4.x; fo.y += ni4.y + nj4.y;
            fo.z += ni4.z + nj4.z; fo.w += ni4.w + nj4.w;
        }
        float sc = (fo.x>0.f?fo.x:0.01f*fo.x)*at.x + (fo.y>0.f?fo.y:0.01f*fo.y)*at.y
                 + (fo.z>0.f?fo.z:0.01f*fo.z)*at.z + (fo.w>0.f?fo.w:0.01f*fo.w)*at.w;
        #pragma unroll
        for (int o=8;o>0;o>>=1) sc += __shfl_down_sync(0xffffffffu, sc, o);
        if ((t & 15) == 0 && valid) g_score[e*4 + (t>>4)] = sc;
        *reinterpret_cast<float4*>(fws + el*FW_STR + 4*t) = fo;
        __syncthreads();

        float fm = 0.25f*(fws[el*FW_STR + t] + fws[el*FW_STR + t + 64] +
                          fws[el*FW_STR + t + 128] + fws[el*FW_STR + t + 192]);
        float s1 = fm, s2 = fm*fm;
        #pragma unroll
        for (int o=16;o>0;o>>=1){
            s1 += __shfl_down_sync(0xffffffffu, s1, o);
            s2 += __shfl_down_sync(0xffffffffu, s2, o);
        }
        if (lane == 0){ sRm[wid] = s1; sRv[wid] = s2; }
        __syncthreads();
        float m   = (sRm[2*g] + sRm[2*g+1]) * 0.015625f;
        float var = (sRv[2*g] + sRv[2*g+1]) * 0.015625f - m*m;
        float v = (fm - m) * rsqrtf(var + 1e-5f);
        float o = v > 0.f ? v : expm1f(v);
        if (valid){
            __nv_bfloat16 hi = __float2bfloat16(o);
            g_fb[(size_t)e*128 + t]      = hi;
            g_fb[(size_t)e*128 + 64 + t] = __float2bfloat16(o - __bfloat162float(hi));
        }
    }
}

// ---------------- small GEMM: out[rows,64] = A[rows,K] @ W[K,64] + bias; optional split out ----------------
__global__ __launch_bounds__(256) void small_gemm(
    const float* __restrict__ A, const float* __restrict__ W,
    const float* __restrict__ bias, float* __restrict__ out,
    __nv_bfloat16* __restrict__ out2, int rows, int K){
    __shared__ float sW[65*64];
    __shared__ float sA[4*65];
    for (int i=threadIdx.x; i<K*64; i+=256) sW[i] = W[i];
    __syncthreads();
    const int col = threadIdx.x & 63;
    const int rl  = threadIdx.x >> 6;
    const float b = bias[col];
    for (int base = blockIdx.x*4; base < rows; base += gridDim.x*4){
        for (int i=threadIdx.x; i<4*K; i+=256){
            int r = i / K, k = i - r*K;
            sA[i] = (base + r < rows) ? A[(base+r)*K + k] : 0.f;
        }
        __syncthreads();
        const int row = base + rl;
        if (row < rows){
            float acc = b;
            for (int k=0;k<K;k++) acc += sA[rl*K + k]*sW[k*64 + col];
            if (out) out[row*64 + col] = acc;
            if (out2){
                __nv_bfloat16 h = __float2bfloat16(acc);
                out2[(size_t)row*128 + col]      = h;
                out2[(size_t)row*128 + 64 + col] = __float2bfloat16(acc - __bfloat162float(h));
            }
        }
        __syncthreads();
    }
}

// ---------------- fused softmax + aggregate + mean-heads + inorm + elu ----------------
__global__ __launch_bounds__(64) void aggregate(const int* __restrict__ src){
    const int n = blockIdx.x, t = threadIdx.x;
    const int w = t >> 5, lane = t & 31;
    const int beg = g_rowptr[n], end = g_rowptr[n+1];
    const float4* SC = reinterpret_cast<const float4*>(g_score);

    float4 mx = make_float4(-3.4e38f,-3.4e38f,-3.4e38f,-3.4e38f);
    for (int i=beg+t; i<end; i+=64){
        float4 s = SC[g_eidx[i]];
        mx.x = fmaxf(mx.x, s.x); mx.y = fmaxf(mx.y, s.y);
        mx.z = fmaxf(mx.z, s.z); mx.w = fmaxf(mx.w, s.w);
    }
    #pragma unroll
    for (int o=16;o>0;o>>=1){
        mx.x = fmaxf(mx.x, __shfl_down_sync(0xffffffffu, mx.x, o));
        mx.y = fmaxf(mx.y, __shfl_down_sync(0xffffffffu, mx.y, o));
        mx.z = fmaxf(mx.z, __shfl_down_sync(0xffffffffu, mx.z, o));
        mx.w = fmaxf(mx.w, __shfl_down_sync(0xffffffffu, mx.w, o));
    }
    __shared__ float4 sM[2];
    __shared__ float4 sD[2];
    if (lane == 0) sM[w] = mx;
    __syncthreads();
    mx.x = fmaxf(sM[0].x, sM[1].x); mx.y = fmaxf(sM[0].y, sM[1].y);
    mx.z = fmaxf(sM[0].z, sM[1].z); mx.w = fmaxf(sM[0].w, sM[1].w);

    float4 dn = make_float4(0.f,0.f,0.f,0.f);
    for (int i=beg+t; i<end; i+=64){
        float4 s = SC[g_eidx[i]];
        dn.x += __expf(s.x-mx.x); dn.y += __expf(s.y-mx.y);
        dn.z += __expf(s.z-mx.z); dn.w += __expf(s.w-mx.w);
    }
    #pragma unroll
    for (int o=16;o>0;o>>=1){
        dn.x += __shfl_down_sync(0xffffffffu, dn.x, o);
        dn.y += __shfl_down_sync(0xffffffffu, dn.y, o);
        dn.z += __shfl_down_sync(0xffffffffu, dn.z, o);
        dn.w += __shfl_down_sync(0xffffffffu, dn.w, o);
    }
    if (lane == 0) sD[w] = dn;
    __syncthreads();
    dn.x = sD[0].x + sD[1].x; dn.y = sD[0].y + sD[1].y;
    dn.z = sD[0].z + sD[1].z; dn.w = sD[0].w + sD[1].w;

    const int q = t >> 4;
    const float mq = (q==0)?mx.x:(q==1)?mx.y:(q==2)?mx.z:mx.w;
    const float dq = (q==0)?dn.x:(q==1)?dn.y:(q==2)?dn.z:dn.w;
    const float rq = (end > beg) ? 1.0f/dq : 0.f;
    float4 acc = make_float4(0.f,0.f,0.f,0.f);
    for (int i=beg; i<end; i++){
        int e = g_eidx[i];
        float a = __expf(g_score[e*4 + q] - mq) * rq;
        float4 hp = reinterpret_cast<const float4*>(g_hp)[src[e]*64 + t];
        acc.x += hp.x*a; acc.y += hp.y*a; acc.z += hp.z*a; acc.w += hp.w*a;
    }

    __shared__ float sAcc[256];
    reinterpret_cast<float4*>(sAcc)[t] = acc;
    __syncthreads();
    float v = 0.25f*(sAcc[t] + sAcc[t+64] + sAcc[t+128] + sAcc[t+192]);
    float s1 = v, s2 = v*v;
    #pragma unroll
    for (int o=16;o>0;o>>=1){
        s1 += __shfl_down_sync(0xffffffffu, s1, o);
        s2 += __shfl_down_sync(0xffffffffu, s2, o);
    }
    __shared__ float sS[4];
    if (lane == 0){ sS[w] = s1; sS[2+w] = s2; }
    __syncthreads();
    float m   = (sS[0]+sS[1]) * 0.015625f;
    float var = (sS[2]+sS[3]) * 0.015625f - m*m;
    float o = (v - m) * rsqrtf(var + 1e-5f);
    o = o > 0.f ? o : expm1f(o);
    g_h[n*64 + t] = o;
    __nv_bfloat16 hi = __float2bfloat16(o);
    g_hb[(size_t)n*128 + t]      = hi;
    g_hb[(size_t)n*128 + 64 + t] = __float2bfloat16(o - __bfloat162float(hi));
}

// ---------------- host ----------------
extern "C" void kernel_launch(void* const* d_in, const int* in_sizes, int n_in,
                              void* d_out, int out_size){
    (void)in_sizes; (void)n_in; (void)out_size;
    const float* x      = (const float*)d_in[0];
    const float* efeat  = (const float*)d_in[1];
    const int*   src    = (const int*)  d_in[2];
    const int*   dst    = (const int*)  d_in[3];
    const float* Wn0    = (const float*)d_in[4];
    const float* bn0    = (const float*)d_in[5];
    const float* We0    = (const float*)d_in[6];
    const float* be0    = (const float*)d_in[7];
    const float* Wnode  = (const float*)d_in[8];
    const float* bnode  = (const float*)d_in[9];
    const float* Wni    = (const float*)d_in[10];
    const float* Wnj    = (const float*)d_in[11];
    const float* Wfij   = (const float*)d_in[12];
    const float* attn   = (const float*)d_in[13];
    const float* bias_e = (const float*)d_in[14];
    const float* Wf     = (const float*)d_in[15];
    const float* bf     = (const float*)d_in[16];

    float *p_h, *p_ni, *p_nj, *p_hp;
    __nv_bfloat16 *p_hb, *p_fb, *p_wb;
    cudaGetSymbolAddress((void**)&p_h,  g_h);
    cudaGetSymbolAddress((void**)&p_ni, g_ni);
    cudaGetSymbolAddress((void**)&p_nj, g_nj);
    cudaGetSymbolAddress((void**)&p_hp, g_hp);
    cudaGetSymbolAddress((void**)&p_hb, g_hb);
    cudaGetSymbolAddress((void**)&p_fb, g_fb);
    cudaGetSymbolAddress((void**)&p_wb, g_wbuf);

    cudaFuncSetAttribute(mma_gemm,   cudaFuncAttributeMaxDynamicSharedMemorySize, MMA_SMEM);
    cudaFuncSetAttribute(edge_fused, cudaFuncAttributeMaxDynamicSharedMemorySize, EF_SMEM);

    // weight images (layer-major: [l*4 + {ni,nj,node,fij}])
    for (int l=0; l<2; l++){
        k_wconv<<<192, 256>>>(Wni   + l*16384, p_wb + (size_t)(l*4+0)*49152);
        k_wconv<<<192, 256>>>(Wnj   + l*16384, p_wb + (size_t)(l*4+1)*49152);
        k_wconv<<<192, 256>>>(Wnode + l*16384, p_wb + (size_t)(l*4+2)*49152);
        k_wconv<<<192, 256>>>(Wfij  + l*16384, p_wb + (size_t)(l*4+3)*49152);
    }

    // CSR by dst
    k_zero_cnt<<<(NN+255)/256, 256>>>();
    k_count<<<(NE+255)/256, 256>>>(dst);
    k_scan<<<1, 1024>>>();
    k_scatter<<<(NE+255)/256, 256>>>(dst);

    // initial embeddings (emit split-bf16 directly)
    small_gemm<<<5000, 256>>>(x,     Wn0, bn0, nullptr, p_hb, NN, 65);
    small_gemm<<<8192, 256>>>(efeat, We0, be0, nullptr, p_fb, NE, 15);

    for (int l=0; l<2; l++){
        mma_gemm<<<dim3(157, 6), 256, MMA_SMEM>>>(
            p_hb, p_wb + (size_t)(l*4+0)*49152, bnode + l*256, p_ni, p_nj, p_hp, NN, 3);
        edge_fused<<<1563, 512, EF_SMEM>>>(
            p_wb + (size_t)(l*4+3)*49152, src, dst, bias_e + l*256, attn + l*256);
        aggregate<<<NN, 64>>>(src);
    }

    // final head
    small_gemm<<<5000, 256>>>(p_h, Wf, bf, (float*)d_out, nullptr, NN, 64);
}

// round 6
// speedup vs baseline: 1.0684x; 1.0684x over previous
#include <cuda_runtime.h>
#include <cuda_bf16.h>
#include <math.h>
#include <stdint.h>

#define NN 20000
#define NE 200000

// ---------------- scratch (device globals; allocation-free rule) ----------------
__device__ __align__(16) float g_h[NN*64];      // node features fp32 (final head input)
__device__ __align__(16) float g_ni[NN*256];
__device__ __align__(16) float g_nj[NN*256];
__device__ __align__(16) float g_hp[NN*256];
__device__ __align__(16) float g_score[NE*4];
__device__ __align__(16) float g_pfm[2*(size_t)NE*64];  // per-half head-mean partials
__device__ int g_rowptr[NN+1];
__device__ int g_cur[NN];
__device__ int g_eidx[NE];
__device__ __align__(16) __nv_bfloat16 g_hb[NN*128];     // [hi|lo] of h
__device__ __align__(16) __nv_bfloat16 g_fb[NE*128];     // [hi|lo] of f
__device__ __align__(16) __nv_bfloat16 g_wbuf[8*49152];  // 8 x [256 n][192 k]

// ---------------- CSR build ----------------
__global__ void k_count(const int* __restrict__ dst){
    int e = blockIdx.x*blockDim.x + threadIdx.x;
    if (e < NE) atomicAdd(&g_cur[dst[e]], 1);
}
__global__ __launch_bounds__(1024) void k_scan(){
    __shared__ int sPart[1024];
    const int t = threadIdx.x;
    const int beg = t*20;
    const int end = (beg+20 < NN) ? beg+20 : NN;
    int s = 0;
    for (int i=beg; i<end; i++) s += g_cur[i];
    sPart[t] = s;
    __syncthreads();
    for (int o=1; o<1024; o<<=1){
        int v = (t >= o) ? sPart[t-o] : 0;
        __syncthreads();
        sPart[t] += v;
        __syncthreads();
    }
    int run = (t==0) ? 0 : sPart[t-1];
    for (int i=beg; i<end; i++){
        int c = g_cur[i];
        g_rowptr[i] = run;
        g_cur[i]    = run;
        run += c;
    }
    if (t == 0) g_rowptr[NN] = NE;
}
__global__ void k_scatter(const int* __restrict__ dst){
    int e = blockIdx.x*blockDim.x + threadIdx.x;
    if (e < NE){
        int p = atomicAdd(&g_cur[dst[e]], 1);
        g_eidx[p] = e;
    }
}

// ---------------- W' images, all 8 in one launch ----------------
__global__ __launch_bounds__(256) void k_wconv_all(
    const float* __restrict__ Wni, const float* __restrict__ Wnj,
    const float* __restrict__ Wnode, const float* __restrict__ Wfij){
    int idx = blockIdx.x*256 + threadIdx.x;       // 49152 per matrix
    if (idx >= 49152) return;
    int m = blockIdx.y;                           // 0..7 = l*4 + {ni,nj,node,fij}
    int l = m >> 2, which = m & 3;
    const float* W = (which==0?Wni: which==1?Wnj: which==2?Wnode: Wfij) + l*16384;
    int n = idx / 192, kk = idx % 192;
    int ks = kk & 63;
    float v = W[ks*256 + n];
    __nv_bfloat16 h = __float2bfloat16(v);
    if (kk >= 128) h = __float2bfloat16(v - __bfloat162float(h));
    g_wbuf[(size_t)m*49152 + n*192 + kk] = h;
}

// ---------------- bf16 HMMA GEMM (nodes): out[rows,256] = split(A) @ W' ----------------
#define MSTR 200
#define MMA_SMEM (2*128*MSTR*2)

__global__ __launch_bounds__(256) void mma_gemm(
    const __nv_bfloat16* __restrict__ ab, const __nv_bfloat16* __restrict__ wimg0,
    const float* __restrict__ bias2,
    float* __restrict__ o0, float* __restrict__ o1, float* __restrict__ o2,
    int rows){
    extern __shared__ __nv_bfloat16 sm[];
    __nv_bfloat16* sA = sm;
    __nv_bfloat16* sW = sm + 128*MSTR;
    const int tid = threadIdx.x;
    const int y = blockIdx.y;
    const int mat = y >> 1;
    const int ch  = y & 1;
    const __nv_bfloat16* wimg = wimg0 + (size_t)mat*49152;
    float* out = (mat==0) ? o0 : (mat==1) ? o1 : o2;
    const float* bias = (mat==2) ? bias2 : nullptr;
    const int row0 = blockIdx.x*128;
    const int cb   = ch*128;

    #pragma unroll
    for (int it=0; it<8; it++){
        int idx = it*256 + tid;
        int r = idx >> 4, c8 = (idx & 15)*8;
        uint4 v = make_uint4(0u,0u,0u,0u);
        if (row0 + r < rows) v = *reinterpret_cast<const uint4*>(ab + (size_t)(row0+r)*128 + c8);
        *reinterpret_cast<uint4*>(sA + r*MSTR + c8) = v;
    }
    #pragma unroll
    for (int it=0; it<4; it++){
        int idx = it*256 + tid;
        int r = idx >> 3, c8 = (idx & 7)*8;
        uint4 v = make_uint4(0u,0u,0u,0u);
        if (row0 + r < rows) v = *reinterpret_cast<const uint4*>(ab + (size_t)(row0+r)*128 + c8);
        *reinterpret_cast<uint4*>(sA + r*MSTR + 128 + c8) = v;
    }
    #pragma unroll
    for (int it=0; it<12; it++){
        int idx = it*256 + tid;
        int n = idx / 24, c8 = (idx % 24)*8;
        uint4 v = *reinterpret_cast<const uint4*>(wimg + (size_t)(cb+n)*192 + c8);
        *reinterpret_cast<uint4*>(sW + n*MSTR + c8) = v;
    }
    __syncthreads();

    const int wid = tid >> 5, lane = tid & 31;
    const int wrow = wid & 1, wcol = wid >> 1;
    const int lr = lane >> 2, lk2 = (lane & 3)*2;

    float acc[4][4][4];
    #pragma unroll
    for (int mi=0;mi<4;mi++)
        #pragma unroll
        for (int ni=0;ni<4;ni++)
            #pragma unroll
            for (int q=0;q<4;q++) acc[mi][ni][q] = 0.f;

    #pragma unroll
    for (int ks=0; ks<12; ks++){
        const int k = ks*16;
        uint32_t afr[4][4];
        #pragma unroll
        for (int mi=0;mi<4;mi++){
            const __nv_bfloat16* ap = sA + (wrow*64 + mi*16 + lr)*MSTR + k + lk2;
            afr[mi][0] = *reinterpret_cast<const uint32_t*>(ap);
            afr[mi][1] = *reinterpret_cast<const uint32_t*>(ap + 8*MSTR);
            afr[mi][2] = *reinterpret_cast<const uint32_t*>(ap + 8);
            afr[mi][3] = *reinterpret_cast<const uint32_t*>(ap + 8*MSTR + 8);
        }
        #pragma unroll
        for (int ni=0;ni<4;ni++){
            const __nv_bfloat16* bp = sW + (wcol*32 + ni*8 + lr)*MSTR + k + lk2;
            uint32_t b0 = *reinterpret_cast<const uint32_t*>(bp);
            uint32_t b1 = *reinterpret_cast<const uint32_t*>(bp + 8);
            #pragma unroll
            for (int mi=0;mi<4;mi++){
                asm volatile(
                    "mma.sync.aligned.m16n8k16.row.col.f32.bf16.bf16.f32 "
                    "{%0,%1,%2,%3}, {%4,%5,%6,%7}, {%8,%9}, {%0,%1,%2,%3};"
                    : "+f"(acc[mi][ni][0]), "+f"(acc[mi][ni][1]),
                      "+f"(acc[mi][ni][2]), "+f"(acc[mi][ni][3])
                    : "r"(afr[mi][0]), "r"(afr[mi][1]), "r"(afr[mi][2]), "r"(afr[mi][3]),
                      "r"(b0), "r"(b1));
            }
        }
    }

    #pragma unroll
    for (int mi=0;mi<4;mi++){
        #pragma unroll
        for (int ni=0;ni<4;ni++){
            int r = row0 + wrow*64 + mi*16 + lr;
            int c = cb + wcol*32 + ni*8 + lk2;
            float bx = 0.f, by = 0.f;
            if (bias){ bx = bias[c]; by = bias[c+1]; }
            if (r < rows){
                float2 v = make_float2(acc[mi][ni][0] + bx, acc[mi][ni][1] + by);
                *reinterpret_cast<float2*>(out + (size_t)r*256 + c) = v;
            }
            if (r + 8 < rows){
                float2 v = make_float2(acc[mi][ni][2] + bx, acc[mi][ni][3] + by);
                *reinterpret_cast<float2*>(out + (size_t)(r+8)*256 + c) = v;
            }
        }
    }
}

// ---------------- edge GEMM + reduced epilogue: scores + head-mean partials ----------------
// Same tile shape as mma_gemm (128 edges x 128 cols, K=192, 2 CTAs/SM). Never materializes fo.
__device__ __forceinline__ float lky(float x){ return x > 0.f ? x : 0.01f*x; }

__global__ __launch_bounds__(256) void edge_gemm(
    const __nv_bfloat16* __restrict__ wimg,    // fij image [256][192]
    const int* __restrict__ src, const int* __restrict__ dst,
    const float* __restrict__ bias_e, const float* __restrict__ attn){
    extern __shared__ __nv_bfloat16 sm[];
    __nv_bfloat16* sA = sm;
    __nv_bfloat16* sW = sm + 128*MSTR;
    const int tid = threadIdx.x;
    const int ch  = blockIdx.y;            // col half: heads 2ch, 2ch+1
    const int cb  = ch*128;
    const int e0  = blockIdx.x*128;

    #pragma unroll
    for (int it=0; it<8; it++){
        int idx = it*256 + tid;
        int r = idx >> 4, c8 = (idx & 15)*8;
        uint4 v = make_uint4(0u,0u,0u,0u);
        if (e0 + r < NE) v = *reinterpret_cast<const uint4*>(g_fb + (size_t)(e0+r)*128 + c8);
        *reinterpret_cast<uint4*>(sA + r*MSTR + c8) = v;
    }
    #pragma unroll
    for (int it=0; it<4; it++){
        int idx = it*256 + tid;
        int r = idx >> 3, c8 = (idx & 7)*8;
        uint4 v = make_uint4(0u,0u,0u,0u);
        if (e0 + r < NE) v = *reinterpret_cast<const uint4*>(g_fb + (size_t)(e0+r)*128 + c8);
        *reinterpret_cast<uint4*>(sA + r*MSTR + 128 + c8) = v;
    }
    #pragma unroll
    for (int it=0; it<12; it++){
        int idx = it*256 + tid;
        int n = idx / 24, c8 = (idx % 24)*8;
        uint4 v = *reinterpret_cast<const uint4*>(wimg + (size_t)(cb+n)*192 + c8);
        *reinterpret_cast<uint4*>(sW + n*MSTR + c8) = v;
    }
    __syncthreads();

    const int wid = tid >> 5, lane = tid & 31;
    const int wrow = wid & 1, wcol = wid >> 1;
    const int lr = lane >> 2, lk2 = (lane & 3)*2;

    float acc[4][4][4];
    #pragma unroll
    for (int mi=0;mi<4;mi++)
        #pragma unroll
        for (int ni=0;ni<4;ni++)
            #pragma unroll
            for (int q=0;q<4;q++) acc[mi][ni][q] = 0.f;

    #pragma unroll
    for (int ks=0; ks<12; ks++){
        const int k = ks*16;
        uint32_t afr[4][4];
        #pragma unroll
        for (int mi=0;mi<4;mi++){
            const __nv_bfloat16* ap = sA + (wrow*64 + mi*16 + lr)*MSTR + k + lk2;
            afr[mi][0] = *reinterpret_cast<const uint32_t*>(ap);
            afr[mi][1] = *reinterpret_cast<const uint32_t*>(ap + 8*MSTR);
            afr[mi][2] = *reinterpret_cast<const uint32_t*>(ap + 8);
            afr[mi][3] = *reinterpret_cast<const uint32_t*>(ap + 8*MSTR + 8);
        }
        #pragma unroll
        for (int ni=0;ni<4;ni++){
            const __nv_bfloat16* bp = sW + (wcol*32 + ni*8 + lr)*MSTR + k + lk2;
            uint32_t b0 = *reinterpret_cast<const uint32_t*>(bp);
            uint32_t b1 = *reinterpret_cast<const uint32_t*>(bp + 8);
            #pragma unroll
            for (int mi=0;mi<4;mi++){
                asm volatile(
                    "mma.sync.aligned.m16n8k16.row.col.f32.bf16.bf16.f32 "
                    "{%0,%1,%2,%3}, {%4,%5,%6,%7}, {%8,%9}, {%0,%1,%2,%3};"
                    : "+f"(acc[mi][ni][0]), "+f"(acc[mi][ni][1]),
                      "+f"(acc[mi][ni][2]), "+f"(acc[mi][ni][3])
                    : "r"(afr[mi][0]), "r"(afr[mi][1]), "r"(afr[mi][2]), "r"(afr[mi][3]),
                      "r"(b0), "r"(b1));
            }
        }
    }
    __syncthreads();   // sA/sW dead; overlay reduction buffers

    float* sFm = reinterpret_cast<float*>(sm);            // [128][65]
    float* sSc = reinterpret_cast<float*>(sm) + 128*65;   // [128][4]

    // fo = acc + bias_e + ni[src] + nj[dst]; score partials per row
    float scp[4][2];
    #pragma unroll
    for (int mi=0;mi<4;mi++){ scp[mi][0] = 0.f; scp[mi][1] = 0.f; }
    #pragma unroll
    for (int mi=0;mi<4;mi++){
        int rl = wrow*64 + mi*16 + lr;
        int e1 = e0 + rl, e2 = e1 + 8;
        int s1 = (e1 < NE) ? src[e1] : 0, d1 = (e1 < NE) ? dst[e1] : 0;
        int s2 = (e2 < NE) ? src[e2] : 0, d2 = (e2 < NE) ? dst[e2] : 0;
        #pragma unroll
        for (int ni=0;ni<4;ni++){
            int gc = cb + wcol*32 + ni*8 + lk2;
            float2 bi = *reinterpret_cast<const float2*>(bias_e + gc);
            float2 av = *reinterpret_cast<const float2*>(attn + gc);
            float2 n1 = *reinterpret_cast<const float2*>(g_ni + (size_t)s1*256 + gc);
            float2 j1 = *reinterpret_cast<const float2*>(g_nj + (size_t)d1*256 + gc);
            float2 n2 = *reinterpret_cast<const float2*>(g_ni + (size_t)s2*256 + gc);
            float2 j2 = *reinterpret_cast<const float2*>(g_nj + (size_t)d2*256 + gc);
            acc[mi][ni][0] += bi.x + n1.x + j1.x;
            acc[mi][ni][1] += bi.y + n1.y + j1.y;
            acc[mi][ni][2] += bi.x + n2.x + j2.x;
            acc[mi][ni][3] += bi.y + n2.y + j2.y;
            scp[mi][0] += lky(acc[mi][ni][0])*av.x + lky(acc[mi][ni][1])*av.y;
            scp[mi][1] += lky(acc[mi][ni][2])*av.x + lky(acc[mi][ni][3])*av.y;
        }
    }
    // reduce over the 4-lane col group (lanes differ in lane&3)
    #pragma unroll
    for (int mi=0;mi<4;mi++){
        #pragma unroll
        for (int p=0;p<2;p++){
            float v = scp[mi][p];
            v += __shfl_xor_sync(0xffffffffu, v, 1);
            v += __shfl_xor_sync(0xffffffffu, v, 2);
            scp[mi][p] = v;
        }
    }
    if ((lane & 3) == 0){
        #pragma unroll
        for (int mi=0;mi<4;mi++){
            int rl = wrow*64 + mi*16 + lr;
            sSc[rl*4 + wcol]     = scp[mi][0];
            sSc[(rl+8)*4 + wcol] = scp[mi][1];
        }
    }
    // head-mean partial: sFm[r][t] = 0.25*(fo[t] + fo[64+t]) for this half
    if (wcol < 2){
        #pragma unroll
        for (int mi=0;mi<4;mi++){
            int rl = wrow*64 + mi*16 + lr;
            #pragma unroll
            for (int ni=0;ni<4;ni++){
                int t = wcol*32 + ni*8 + lk2;
                sFm[rl*65 + t]       = 0.25f*acc[mi][ni][0];
                sFm[rl*65 + t + 1]   = 0.25f*acc[mi][ni][1];
                sFm[(rl+8)*65 + t]     = 0.25f*acc[mi][ni][2];
                sFm[(rl+8)*65 + t + 1] = 0.25f*acc[mi][ni][3];
            }
        }
    }
    __syncthreads();
    if (wcol >= 2){
        #pragma unroll
        for (int mi=0;mi<4;mi++){
            int rl = wrow*64 + mi*16 + lr;
            #pragma unroll
            for (int ni=0;ni<4;ni++){
                int t = (wcol-2)*32 + ni*8 + lk2;
                sFm[rl*65 + t]       += 0.25f*acc[mi][ni][0];
                sFm[rl*65 + t + 1]   += 0.25f*acc[mi][ni][1];
                sFm[(rl+8)*65 + t]     += 0.25f*acc[mi][ni][2];
                sFm[(rl+8)*65 + t + 1] += 0.25f*acc[mi][ni][3];
            }
        }
    }
    __syncthreads();

    // write scores (2 heads of this half) and pfm partial
    {
        int r = tid >> 1, hh = tid & 1;
        int e = e0 + r;
        if (e < NE){
            float sv = sSc[r*4 + 2*hh] + sSc[r*4 + 2*hh + 1];
            g_score[(size_t)e*4 + ch*2 + hh] = sv;
        }
    }
    for (int idx = tid; idx < 128*64; idx += 256){
        int r = idx >> 6, t = idx & 63;
        int e = e0 + r;
        if (e < NE) g_pfm[((size_t)ch*NE + e)*64 + t] = sFm[r*65 + t];
    }
}

// ---------------- edge_b: combine partials -> inorm -> elu -> split f ----------------
__global__ __launch_bounds__(256) void edge_b(){
    const int g = threadIdx.x >> 6;
    const int t = threadIdx.x & 63;
    const int e = blockIdx.x*4 + g;
    const int w = threadIdx.x >> 5, lane = threadIdx.x & 31;
    float fm = 0.f;
    if (e < NE)
        fm = g_pfm[(size_t)e*64 + t] + g_pfm[((size_t)NE + e)*64 + t];
    float s1 = fm, s2 = fm*fm;
    #pragma unroll
    for (int o=16;o>0;o>>=1){
        s1 += __shfl_down_sync(0xffffffffu, s1, o);
        s2 += __shfl_down_sync(0xffffffffu, s2, o);
    }
    __shared__ float sRm[8], sRv[8];
    if (lane == 0){ sRm[w] = s1; sRv[w] = s2; }
    __syncthreads();
    float m   = (sRm[2*g] + sRm[2*g+1]) * 0.015625f;
    float var = (sRv[2*g] + sRv[2*g+1]) * 0.015625f - m*m;
    float v = (fm - m) * rsqrtf(var + 1e-5f);
    float o = v > 0.f ? v : expm1f(v);
    if (e < NE){
        __nv_bfloat16 hi = __float2bfloat16(o);
        g_fb[(size_t)e*128 + t]      = hi;
        g_fb[(size_t)e*128 + 64 + t] = __float2bfloat16(o - __bfloat162float(hi));
    }
}

// ---------------- small GEMMs ----------------
// merged initial embeddings: y==0 -> x@Wn0 (split out g_hb), y==1 -> efeat@We0 (split out g_fb)
__global__ __launch_bounds__(256) void sg_init(
    const float* __restrict__ A0, const float* __restrict__ W0, const float* __restrict__ b0,
    const float* __restrict__ A1, const float* __restrict__ W1, const float* __restrict__ b1){
    const int y = blockIdx.y;
    const float* A = y ? A1 : A0;
    const float* W = y ? W1 : W0;
    const float* bias = y ? b1 : b0;
    __nv_bfloat16* out2 = y ? g_fb : g_hb;
    const int rows = y ? NE : NN;
    const int K    = y ? 15 : 65;
    __shared__ float sW[65*64];
    __shared__ float sA[4*65];
    for (int i=threadIdx.x; i<K*64; i+=256) sW[i] = W[i];
    __syncthreads();
    const int col = threadIdx.x & 63;
    const int rl  = threadIdx.x >> 6;
    const float b = bias[col];
    for (int base = blockIdx.x*4; base < rows; base += gridDim.x*4){
        for (int i=threadIdx.x; i<4*K; i+=256){
            int r = i / K, k = i - r*K;
            sA[i] = (base + r < rows) ? A[(size_t)(base+r)*K + k] : 0.f;
        }
        __syncthreads();
        const int row = base + rl;
        if (row < rows){
            float acc = b;
            for (int k=0;k<K;k++) acc += sA[rl*K + k]*sW[k*64 + col];
            __nv_bfloat16 h = __float2bfloat16(acc);
            out2[(size_t)row*128 + col]      = h;
            out2[(size_t)row*128 + 64 + col] = __float2bfloat16(acc - __bfloat162float(h));
        }
        __syncthreads();
    }
}

// final head
__global__ __launch_bounds__(256) void sg_final(
    const float* __restrict__ W, const float* __restrict__ bias, float* __restrict__ out){
    __shared__ float sW[64*64];
    __shared__ float sA[4*64];
    for (int i=threadIdx.x; i<64*64; i+=256) sW[i] = W[i];
    __syncthreads();
    const int col = threadIdx.x & 63;
    const int rl  = threadIdx.x >> 6;
    const float b = bias[col];
    for (int base = blockIdx.x*4; base < NN; base += gridDim.x*4){
        for (int i=threadIdx.x; i<4*64; i+=256){
            int r = i >> 6, k = i & 63;
            sA[i] = (base + r < NN) ? g_h[(base+r)*64 + k] : 0.f;
        }
        __syncthreads();
        const int row = base + rl;
        if (row < NN){
            float acc = b;
            for (int k=0;k<64;k++) acc += sA[rl*64 + k]*sW[k*64 + col];
            out[row*64 + col] = acc;
        }
        __syncthreads();
    }
}

// ---------------- fused softmax + aggregate + mean-heads + inorm + elu ----------------
__global__ __launch_bounds__(64) void aggregate(const int* __restrict__ src){
    const int n = blockIdx.x, t = threadIdx.x;
    const int w = t >> 5, lane = t & 31;
    const int beg = g_rowptr[n], end = g_rowptr[n+1];
    const float4* SC = reinterpret_cast<const float4*>(g_score);

    float4 mx = make_float4(-3.4e38f,-3.4e38f,-3.4e38f,-3.4e38f);
    for (int i=beg+t; i<end; i+=64){
        float4 s = SC[g_eidx[i]];
        mx.x = fmaxf(mx.x, s.x); mx.y = fmaxf(mx.y, s.y);
        mx.z = fmaxf(mx.z, s.z); mx.w = fmaxf(mx.w, s.w);
    }
    #pragma unroll
    for (int o=16;o>0;o>>=1){
        mx.x = fmaxf(mx.x, __shfl_down_sync(0xffffffffu, mx.x, o));
        mx.y = fmaxf(mx.y, __shfl_down_sync(0xffffffffu, mx.y, o));
        mx.z = fmaxf(mx.z, __shfl_down_sync(0xffffffffu, mx.z, o));
        mx.w = fmaxf(mx.w, __shfl_down_sync(0xffffffffu, mx.w, o));
    }
    __shared__ float4 sM[2];
    __shared__ float4 sD[2];
    if (lane == 0) sM[w] = mx;
    __syncthreads();
    mx.x = fmaxf(sM[0].x, sM[1].x); mx.y = fmaxf(sM[0].y, sM[1].y);
    mx.z = fmaxf(sM[0].z, sM[1].z); mx.w = fmaxf(sM[0].w, sM[1].w);

    float4 dn = make_float4(0.f,0.f,0.f,0.f);
    for (int i=beg+t; i<end; i+=64){
        float4 s = SC[g_eidx[i]];
        dn.x += __expf(s.x-mx.x); dn.y += __expf(s.y-mx.y);
        dn.z += __expf(s.z-mx.z); dn.w += __expf(s.w-mx.w);
    }
    #pragma unroll
    for (int o=16;o>0;o>>=1){
        dn.x += __shfl_down_sync(0xffffffffu, dn.x, o);
        dn.y += __shfl_down_sync(0xffffffffu, dn.y, o);
        dn.z += __shfl_down_sync(0xffffffffu, dn.z, o);
        dn.w += __shfl_down_sync(0xffffffffu, dn.w, o);
    }
    if (lane == 0) sD[w] = dn;
    __syncthreads();
    dn.x = sD[0].x + sD[1].x; dn.y = sD[0].y + sD[1].y;
    dn.z = sD[0].z + sD[1].z; dn.w = sD[0].w + sD[1].w;

    const int q = t >> 4;
    const float mq = (q==0)?mx.x:(q==1)?mx.y:(q==2)?mx.z:mx.w;
    const float dq = (q==0)?dn.x:(q==1)?dn.y:(q==2)?dn.z:dn.w;
    const float rq = (end > beg) ? 1.0f/dq : 0.f;
    float4 acc = make_float4(0.f,0.f,0.f,0.f);
    for (int i=beg; i<end; i++){
        int e = g_eidx[i];
        float a = __expf(g_score[(size_t)e*4 + q] - mq) * rq;
        float4 hp = reinterpret_cast<const float4*>(g_hp)[src[e]*64 + t];
        acc.x += hp.x*a; acc.y += hp.y*a; acc.z += hp.z*a; acc.w += hp.w*a;
    }

    __shared__ float sAcc[256];
    reinterpret_cast<float4*>(sAcc)[t] = acc;
    __syncthreads();
    float v = 0.25f*(sAcc[t] + sAcc[t+64] + sAcc[t+128] + sAcc[t+192]);
    float s1 = v, s2 = v*v;
    #pragma unroll
    for (int o=16;o>0;o>>=1){
        s1 += __shfl_down_sync(0xffffffffu, s1, o);
        s2 += __shfl_down_sync(0xffffffffu, s2, o);
    }
    __shared__ float sS[4];
    if (lane == 0){ sS[w] = s1; sS[2+w] = s2; }
    __syncthreads();
    float m   = (sS[0]+sS[1]) * 0.015625f;
    float var = (sS[2]+sS[3]) * 0.015625f - m*m;
    float o = (v - m) * rsqrtf(var + 1e-5f);
    o = o > 0.f ? o : expm1f(o);
    g_h[n*64 + t] = o;
    __nv_bfloat16 hi = __float2bfloat16(o);
    g_hb[(size_t)n*128 + t]      = hi;
    g_hb[(size_t)n*128 + 64 + t] = __float2bfloat16(o - __bfloat162float(hi));
}

// ---------------- host ----------------
extern "C" void kernel_launch(void* const* d_in, const int* in_sizes, int n_in,
                              void* d_out, int out_size){
    (void)in_sizes; (void)n_in; (void)out_size;
    const float* x      = (const float*)d_in[0];
    const float* efeat  = (const float*)d_in[1];
    const int*   src    = (const int*)  d_in[2];
    const int*   dst    = (const int*)  d_in[3];
    const float* Wn0    = (const float*)d_in[4];
    const float* bn0    = (const float*)d_in[5];
    const float* We0    = (const float*)d_in[6];
    const float* be0    = (const float*)d_in[7];
    const float* Wnode  = (const float*)d_in[8];
    const float* bnode  = (const float*)d_in[9];
    const float* Wni    = (const float*)d_in[10];
    const float* Wnj    = (const float*)d_in[11];
    const float* Wfij   = (const float*)d_in[12];
    const float* attn   = (const float*)d_in[13];
    const float* bias_e = (const float*)d_in[14];
    const float* Wf     = (const float*)d_in[15];
    const float* bf     = (const float*)d_in[16];

    float *p_ni, *p_nj, *p_hp;
    __nv_bfloat16 *p_hb, *p_wb;
    int* p_cur;
    cudaGetSymbolAddress((void**)&p_ni, g_ni);
    cudaGetSymbolAddress((void**)&p_nj, g_nj);
    cudaGetSymbolAddress((void**)&p_hp, g_hp);
    cudaGetSymbolAddress((void**)&p_hb, g_hb);
    cudaGetSymbolAddress((void**)&p_wb, g_wbuf);
    cudaGetSymbolAddress((void**)&p_cur, g_cur);

    cudaFuncSetAttribute(mma_gemm,  cudaFuncAttributeMaxDynamicSharedMemorySize, MMA_SMEM);
    cudaFuncSetAttribute(edge_gemm, cudaFuncAttributeMaxDynamicSharedMemorySize, MMA_SMEM);

    // launch 0: all weight images
    k_wconv_all<<<dim3(192, 8), 256>>>(Wni, Wnj, Wnode, Wfij);
    // CSR by dst (memset is a graph memset node, not a kernel launch)
    cudaMemsetAsync(p_cur, 0, NN*sizeof(int));
    k_count<<<(NE+255)/256, 256>>>(dst);                       // 1
    k_scan<<<1, 1024>>>();                                     // 2
    k_scatter<<<(NE+255)/256, 256>>>(dst);                     // 3
    // launch 4: both initial embeddings (split-bf16 out)
    sg_init<<<dim3(8192, 2), 256>>>(x, Wn0, bn0, efeat, We0, be0);

    for (int l=0; l<2; l++){
        // launch 5 (layer 0): the node GEMMs -> profiled by ncu -s 5
        mma_gemm<<<dim3(157, 6), 256, MMA_SMEM>>>(
            p_hb, p_wb + (size_t)(l*4)*49152, bnode + l*256, p_ni, p_nj, p_hp, NN);
        edge_gemm<<<dim3(1563, 2), 256, MMA_SMEM>>>(
            p_wb + (size_t)(l*4+3)*49152, src, dst, bias_e + l*256, attn + l*256);
        edge_b<<<(NE+3)/4, 256>>>();
        aggregate<<<NN, 64>>>(src);
    }

    sg_final<<<5000, 256>>>(Wf, bf, (float*)d_out);
}

// round 7
// speedup vs baseline: 1.1018x; 1.0312x over previous
#include <cuda_runtime.h>
#include <cuda_bf16.h>
#include <math.h>
#include <stdint.h>

#define NN 20000
#define NE 200000

// ---------------- scratch (device globals; allocation-free rule) ----------------
__device__ __align__(16) float g_h[NN*64];      // node features fp32 (final head input)
__device__ __align__(16) float g_ni[NN*256];
__device__ __align__(16) float g_nj[NN*256];
__device__ __align__(16) float g_hp[NN*256];
__device__ __align__(16) float g_score[NE*4];
__device__ __align__(16) float g_pfm[2*(size_t)NE*64];  // per-half head-mean partials
__device__ int g_rowptr[NN+1];
__device__ int g_cur[NN];
__device__ int g_eidx[NE];
__device__ __align__(16) __nv_bfloat16 g_hb[NN*128];     // [hi|lo] of h
__device__ __align__(16) __nv_bfloat16 g_fb[NE*128];     // [hi|lo] of f
__device__ __align__(16) __nv_bfloat16 g_wbuf[8*49152];  // 8 x [256 n][192 k]

// ---------------- CSR build ----------------
__global__ void k_count(const int* __restrict__ dst){
    int e = blockIdx.x*blockDim.x + threadIdx.x;
    if (e < NE) atomicAdd(&g_cur[dst[e]], 1);
}
__global__ __launch_bounds__(1024) void k_scan(){
    __shared__ int sPart[1024];
    const int t = threadIdx.x;
    const int beg = t*20;
    const int end = (beg+20 < NN) ? beg+20 : NN;
    int s = 0;
    for (int i=beg; i<end; i++) s += g_cur[i];
    sPart[t] = s;
    __syncthreads();
    for (int o=1; o<1024; o<<=1){
        int v = (t >= o) ? sPart[t-o] : 0;
        __syncthreads();
        sPart[t] += v;
        __syncthreads();
    }
    int run = (t==0) ? 0 : sPart[t-1];
    for (int i=beg; i<end; i++){
        int c = g_cur[i];
        g_rowptr[i] = run;
        g_cur[i]    = run;
        run += c;
    }
    if (t == 0) g_rowptr[NN] = NE;
}
__global__ void k_scatter(const int* __restrict__ dst){
    int e = blockIdx.x*blockDim.x + threadIdx.x;
    if (e < NE){
        int p = atomicAdd(&g_cur[dst[e]], 1);
        g_eidx[p] = e;
    }
}

// ---------------- W' images, all 8 in one launch ----------------
__global__ __launch_bounds__(256) void k_wconv_all(
    const float* __restrict__ Wni, const float* __restrict__ Wnj,
    const float* __restrict__ Wnode, const float* __restrict__ Wfij){
    int idx = blockIdx.x*256 + threadIdx.x;       // 49152 per matrix
    if (idx >= 49152) return;
    int m = blockIdx.y;                           // 0..7 = l*4 + {ni,nj,node,fij}
    int l = m >> 2, which = m & 3;
    const float* W = (which==0?Wni: which==1?Wnj: which==2?Wnode: Wfij) + l*16384;
    int n = idx / 192, kk = idx % 192;
    int ks = kk & 63;
    float v = W[ks*256 + n];
    __nv_bfloat16 h = __float2bfloat16(v);
    if (kk >= 128) h = __float2bfloat16(v - __bfloat162float(h));
    g_wbuf[(size_t)m*49152 + n*192 + kk] = h;
}

// ---------------- bf16 HMMA GEMM (nodes): out[rows,256] = split(A) @ W' ----------------
#define MSTR 200
#define MMA_SMEM (2*128*MSTR*2)

__global__ __launch_bounds__(256) void mma_gemm(
    const __nv_bfloat16* __restrict__ ab, const __nv_bfloat16* __restrict__ wimg0,
    const float* __restrict__ bias2,
    float* __restrict__ o0, float* __restrict__ o1, float* __restrict__ o2,
    int rows){
    extern __shared__ __nv_bfloat16 sm[];
    __nv_bfloat16* sA = sm;
    __nv_bfloat16* sW = sm + 128*MSTR;
    const int tid = threadIdx.x;
    const int y = blockIdx.y;
    const int mat = y >> 1;
    const int ch  = y & 1;
    const __nv_bfloat16* wimg = wimg0 + (size_t)mat*49152;
    float* out = (mat==0) ? o0 : (mat==1) ? o1 : o2;
    const float* bias = (mat==2) ? bias2 : nullptr;
    const int row0 = blockIdx.x*128;
    const int cb   = ch*128;

    #pragma unroll
    for (int it=0; it<8; it++){
        int idx = it*256 + tid;
        int r = idx >> 4, c8 = (idx & 15)*8;
        uint4 v = make_uint4(0u,0u,0u,0u);
        if (row0 + r < rows) v = *reinterpret_cast<const uint4*>(ab + (size_t)(row0+r)*128 + c8);
        *reinterpret_cast<uint4*>(sA + r*MSTR + c8) = v;
    }
    #pragma unroll
    for (int it=0; it<4; it++){
        int idx = it*256 + tid;
        int r = idx >> 3, c8 = (idx & 7)*8;
        uint4 v = make_uint4(0u,0u,0u,0u);
        if (row0 + r < rows) v = *reinterpret_cast<const uint4*>(ab + (size_t)(row0+r)*128 + c8);
        *reinterpret_cast<uint4*>(sA + r*MSTR + 128 + c8) = v;
    }
    #pragma unroll
    for (int it=0; it<12; it++){
        int idx = it*256 + tid;
        int n = idx / 24, c8 = (idx % 24)*8;
        uint4 v = *reinterpret_cast<const uint4*>(wimg + (size_t)(cb+n)*192 + c8);
        *reinterpret_cast<uint4*>(sW + n*MSTR + c8) = v;
    }
    __syncthreads();

    const int wid = tid >> 5, lane = tid & 31;
    const int wrow = wid & 1, wcol = wid >> 1;
    const int lr = lane >> 2, lk2 = (lane & 3)*2;

    float acc[4][4][4];
    #pragma unroll
    for (int mi=0;mi<4;mi++)
        #pragma unroll
        for (int ni=0;ni<4;ni++)
            #pragma unroll
            for (int q=0;q<4;q++) acc[mi][ni][q] = 0.f;

    #pragma unroll
    for (int ks=0; ks<12; ks++){
        const int k = ks*16;
        uint32_t afr[4][4];
        #pragma unroll
        for (int mi=0;mi<4;mi++){
            const __nv_bfloat16* ap = sA + (wrow*64 + mi*16 + lr)*MSTR + k + lk2;
            afr[mi][0] = *reinterpret_cast<const uint32_t*>(ap);
            afr[mi][1] = *reinterpret_cast<const uint32_t*>(ap + 8*MSTR);
            afr[mi][2] = *reinterpret_cast<const uint32_t*>(ap + 8);
            afr[mi][3] = *reinterpret_cast<const uint32_t*>(ap + 8*MSTR + 8);
        }
        #pragma unroll
        for (int ni=0;ni<4;ni++){
            const __nv_bfloat16* bp = sW + (wcol*32 + ni*8 + lr)*MSTR + k + lk2;
            uint32_t b0 = *reinterpret_cast<const uint32_t*>(bp);
            uint32_t b1 = *reinterpret_cast<const uint32_t*>(bp + 8);
            #pragma unroll
            for (int mi=0;mi<4;mi++){
                asm volatile(
                    "mma.sync.aligned.m16n8k16.row.col.f32.bf16.bf16.f32 "
                    "{%0,%1,%2,%3}, {%4,%5,%6,%7}, {%8,%9}, {%0,%1,%2,%3};"
                    : "+f"(acc[mi][ni][0]), "+f"(acc[mi][ni][1]),
                      "+f"(acc[mi][ni][2]), "+f"(acc[mi][ni][3])
                    : "r"(afr[mi][0]), "r"(afr[mi][1]), "r"(afr[mi][2]), "r"(afr[mi][3]),
                      "r"(b0), "r"(b1));
            }
        }
    }

    #pragma unroll
    for (int mi=0;mi<4;mi++){
        #pragma unroll
        for (int ni=0;ni<4;ni++){
            int r = row0 + wrow*64 + mi*16 + lr;
            int c = cb + wcol*32 + ni*8 + lk2;
            float bx = 0.f, by = 0.f;
            if (bias){ bx = bias[c]; by = bias[c+1]; }
            if (r < rows){
                float2 v = make_float2(acc[mi][ni][0] + bx, acc[mi][ni][1] + by);
                *reinterpret_cast<float2*>(out + (size_t)r*256 + c) = v;
            }
            if (r + 8 < rows){
                float2 v = make_float2(acc[mi][ni][2] + bx, acc[mi][ni][3] + by);
                *reinterpret_cast<float2*>(out + (size_t)(r+8)*256 + c) = v;
            }
        }
    }
}

// ---------------- edge GEMM + warp-per-edge epilogue: scores + head-mean partials ----------------
__device__ __forceinline__ float lky(float x){ return x > 0.f ? x : 0.01f*x; }
#define FOSTR 132

__global__ __launch_bounds__(256) void edge_gemm(
    const __nv_bfloat16* __restrict__ wimg,    // fij image [256][192]
    const int* __restrict__ src, const int* __restrict__ dst,
    const float* __restrict__ bias_e, const float* __restrict__ attn){
    extern __shared__ __nv_bfloat16 sm[];
    __nv_bfloat16* sA = sm;
    __nv_bfloat16* sW = sm + 128*MSTR;
    const int tid = threadIdx.x;
    const int ch  = blockIdx.y;            // col half: heads 2ch, 2ch+1
    const int cb  = ch*128;
    const int e0  = blockIdx.x*128;

    #pragma unroll
    for (int it=0; it<8; it++){
        int idx = it*256 + tid;
        int r = idx >> 4, c8 = (idx & 15)*8;
        uint4 v = make_uint4(0u,0u,0u,0u);
        if (e0 + r < NE) v = *reinterpret_cast<const uint4*>(g_fb + (size_t)(e0+r)*128 + c8);
        *reinterpret_cast<uint4*>(sA + r*MSTR + c8) = v;
    }
    #pragma unroll
    for (int it=0; it<4; it++){
        int idx = it*256 + tid;
        int r = idx >> 3, c8 = (idx & 7)*8;
        uint4 v = make_uint4(0u,0u,0u,0u);
        if (e0 + r < NE) v = *reinterpret_cast<const uint4*>(g_fb + (size_t)(e0+r)*128 + c8);
        *reinterpret_cast<uint4*>(sA + r*MSTR + 128 + c8) = v;
    }
    #pragma unroll
    for (int it=0; it<12; it++){
        int idx = it*256 + tid;
        int n = idx / 24, c8 = (idx % 24)*8;
        uint4 v = *reinterpret_cast<const uint4*>(wimg + (size_t)(cb+n)*192 + c8);
        *reinterpret_cast<uint4*>(sW + n*MSTR + c8) = v;
    }
    __syncthreads();

    const int wid = tid >> 5, lane = tid & 31;
    const int wrow = wid & 1, wcol = wid >> 1;
    const int lr = lane >> 2, lk2 = (lane & 3)*2;

    float acc[4][4][4];
    #pragma unroll
    for (int mi=0;mi<4;mi++)
        #pragma unroll
        for (int ni=0;ni<4;ni++)
            #pragma unroll
            for (int q=0;q<4;q++) acc[mi][ni][q] = 0.f;

    #pragma unroll
    for (int ks=0; ks<12; ks++){
        const int k = ks*16;
        uint32_t afr[4][4];
        #pragma unroll
        for (int mi=0;mi<4;mi++){
            const __nv_bfloat16* ap = sA + (wrow*64 + mi*16 + lr)*MSTR + k + lk2;
            afr[mi][0] = *reinterpret_cast<const uint32_t*>(ap);
            afr[mi][1] = *reinterpret_cast<const uint32_t*>(ap + 8*MSTR);
            afr[mi][2] = *reinterpret_cast<const uint32_t*>(ap + 8);
            afr[mi][3] = *reinterpret_cast<const uint32_t*>(ap + 8*MSTR + 8);
        }
        #pragma unroll
        for (int ni=0;ni<4;ni++){
            const __nv_bfloat16* bp = sW + (wcol*32 + ni*8 + lr)*MSTR + k + lk2;
            uint32_t b0 = *reinterpret_cast<const uint32_t*>(bp);
            uint32_t b1 = *reinterpret_cast<const uint32_t*>(bp + 8);
            #pragma unroll
            for (int mi=0;mi<4;mi++){
                asm volatile(
                    "mma.sync.aligned.m16n8k16.row.col.f32.bf16.bf16.f32 "
                    "{%0,%1,%2,%3}, {%4,%5,%6,%7}, {%8,%9}, {%0,%1,%2,%3};"
                    : "+f"(acc[mi][ni][0]), "+f"(acc[mi][ni][1]),
                      "+f"(acc[mi][ni][2]), "+f"(acc[mi][ni][3])
                    : "r"(afr[mi][0]), "r"(afr[mi][1]), "r"(afr[mi][2]), "r"(afr[mi][3]),
                      "r"(b0), "r"(b1));
            }
        }
    }
    __syncthreads();   // sA/sW dead

    // stage fo = acc + bias into smem [128][FOSTR]
    float* sFo = reinterpret_cast<float*>(sm);
    #pragma unroll
    for (int mi=0;mi<4;mi++){
        int rl = wrow*64 + mi*16 + lr;
        #pragma unroll
        for (int ni=0;ni<4;ni++){
            int c = wcol*32 + ni*8 + lk2;
            float2 bi = *reinterpret_cast<const float2*>(bias_e + cb + c);
            sFo[rl*FOSTR + c]         = acc[mi][ni][0] + bi.x;
            sFo[rl*FOSTR + c + 1]     = acc[mi][ni][1] + bi.y;
            sFo[(rl+8)*FOSTR + c]     = acc[mi][ni][2] + bi.x;
            sFo[(rl+8)*FOSTR + c + 1] = acc[mi][ni][3] + bi.y;
        }
    }
    __syncthreads();

    // warp-per-edge: warp wid handles edges wid*16 .. wid*16+15
    const float4 at4 = *reinterpret_cast<const float4*>(attn + cb + 4*lane);
    #pragma unroll 1
    for (int it=0; it<16; it++){
        const int el = wid*16 + it;
        const int e  = e0 + el;
        if (e >= NE) break;   // uniform per warp
        const int s = src[e], d = dst[e];
        float4 fo = *reinterpret_cast<const float4*>(sFo + el*FOSTR + 4*lane);
        float4 n4 = *reinterpret_cast<const float4*>(g_ni + (size_t)s*256 + cb + 4*lane);
        float4 j4 = *reinterpret_cast<const float4*>(g_nj + (size_t)d*256 + cb + 4*lane);
        fo.x += n4.x + j4.x; fo.y += n4.y + j4.y;
        fo.z += n4.z + j4.z; fo.w += n4.w + j4.w;
        // per-head score: lanes 0-15 = head 2ch, lanes 16-31 = head 2ch+1
        float p = lky(fo.x)*at4.x + lky(fo.y)*at4.y + lky(fo.z)*at4.z + lky(fo.w)*at4.w;
        p += __shfl_xor_sync(0xffffffffu, p, 8);
        p += __shfl_xor_sync(0xffffffffu, p, 4);
        p += __shfl_xor_sync(0xffffffffu, p, 2);
        p += __shfl_xor_sync(0xffffffffu, p, 1);
        if (lane == 0)  g_score[(size_t)e*4 + 2*ch]     = p;
        if (lane == 16) g_score[(size_t)e*4 + 2*ch + 1] = p;
        // head-mean partial for this half: 0.25*(fo[t] + fo[t+64]), t = lane*4 (lanes 0-15)
        float4 ot;
        ot.x = __shfl_xor_sync(0xffffffffu, fo.x, 16);
        ot.y = __shfl_xor_sync(0xffffffffu, fo.y, 16);
        ot.z = __shfl_xor_sync(0xffffffffu, fo.z, 16);
        ot.w = __shfl_xor_sync(0xffffffffu, fo.w, 16);
        if (lane < 16){
            float4 hm = make_float4(0.25f*(fo.x+ot.x), 0.25f*(fo.y+ot.y),
                                    0.25f*(fo.z+ot.z), 0.25f*(fo.w+ot.w));
            *reinterpret_cast<float4*>(g_pfm + ((size_t)ch*NE + e)*64 + 4*lane) = hm;
        }
    }
}

// ---------------- edge_b: combine partials -> inorm -> elu -> split f ----------------
__global__ __launch_bounds__(256) void edge_b(){
    const int g = threadIdx.x >> 6;
    const int t = threadIdx.x & 63;
    const int e = blockIdx.x*4 + g;
    const int w = threadIdx.x >> 5, lane = threadIdx.x & 31;
    float fm = 0.f;
    if (e < NE)
        fm = g_pfm[(size_t)e*64 + t] + g_pfm[((size_t)NE + e)*64 + t];
    float s1 = fm, s2 = fm*fm;
    #pragma unroll
    for (int o=16;o>0;o>>=1){
        s1 += __shfl_down_sync(0xffffffffu, s1, o);
        s2 += __shfl_down_sync(0xffffffffu, s2, o);
    }
    __shared__ float sRm[8], sRv[8];
    if (lane == 0){ sRm[w] = s1; sRv[w] = s2; }
    __syncthreads();
    float m   = (sRm[2*g] + sRm[2*g+1]) * 0.015625f;
    float var = (sRv[2*g] + sRv[2*g+1]) * 0.015625f - m*m;
    float v = (fm - m) * rsqrtf(var + 1e-5f);
    float o = v > 0.f ? v : expm1f(v);
    if (e < NE){
        __nv_bfloat16 hi = __float2bfloat16(o);
        g_fb[(size_t)e*128 + t]      = hi;
        g_fb[(size_t)e*128 + 64 + t] = __float2bfloat16(o - __bfloat162float(hi));
    }
}

// ---------------- small GEMMs ----------------
__global__ __launch_bounds__(256) void sg_init(
    const float* __restrict__ A0, const float* __restrict__ W0, const float* __restrict__ b0,
    const float* __restrict__ A1, const float* __restrict__ W1, const float* __restrict__ b1){
    const int y = blockIdx.y;
    const float* A = y ? A1 : A0;
    const float* W = y ? W1 : W0;
    const float* bias = y ? b1 : b0;
    __nv_bfloat16* out2 = y ? g_fb : g_hb;
    const int rows = y ? NE : NN;
    const int K    = y ? 15 : 65;
    __shared__ float sW[65*64];
    __shared__ float sA[4*65];
    for (int i=threadIdx.x; i<K*64; i+=256) sW[i] = W[i];
    __syncthreads();
    const int col = threadIdx.x & 63;
    const int rl  = threadIdx.x >> 6;
    const float b = bias[col];
    for (int base = blockIdx.x*4; base < rows; base += gridDim.x*4){
        for (int i=threadIdx.x; i<4*K; i+=256){
            int r = i / K, k = i - r*K;
            sA[i] = (base + r < rows) ? A[(size_t)(base+r)*K + k] : 0.f;
        }
        __syncthreads();
        const int row = base + rl;
        if (row < rows){
            float acc = b;
            for (int k=0;k<K;k++) acc += sA[rl*K + k]*sW[k*64 + col];
            __nv_bfloat16 h = __float2bfloat16(acc);
            out2[(size_t)row*128 + col]      = h;
            out2[(size_t)row*128 + 64 + col] = __float2bfloat16(acc - __bfloat162float(h));
        }
        __syncthreads();
    }
}

__global__ __launch_bounds__(256) void sg_final(
    const float* __restrict__ W, const float* __restrict__ bias, float* __restrict__ out){
    __shared__ float sW[64*64];
    __shared__ float sA[4*64];
    for (int i=threadIdx.x; i<64*64; i+=256) sW[i] = W[i];
    __syncthreads();
    const int col = threadIdx.x & 63;
    const int rl  = threadIdx.x >> 6;
    const float b = bias[col];
    for (int base = blockIdx.x*4; base < NN; base += gridDim.x*4){
        for (int i=threadIdx.x; i<4*64; i+=256){
            int r = i >> 6, k = i & 63;
            sA[i] = (base + r < NN) ? g_h[(base+r)*64 + k] : 0.f;
        }
        __syncthreads();
        const int row = base + rl;
        if (row < NN){
            float acc = b;
            for (int k=0;k<64;k++) acc += sA[rl*64 + k]*sW[k*64 + col];
            out[row*64 + col] = acc;
        }
        __syncthreads();
    }
}

// ---------------- fused softmax + aggregate + mean-heads + inorm + elu ----------------
__global__ __launch_bounds__(64) void aggregate(const int* __restrict__ src){
    const int n = blockIdx.x, t = threadIdx.x;
    const int w = t >> 5, lane = t & 31;
    const int beg = g_rowptr[n], end = g_rowptr[n+1];
    const float4* SC = reinterpret_cast<const float4*>(g_score);

    float4 mx = make_float4(-3.4e38f,-3.4e38f,-3.4e38f,-3.4e38f);
    for (int i=beg+t; i<end; i+=64){
        float4 s = SC[g_eidx[i]];
        mx.x = fmaxf(mx.x, s.x); mx.y = fmaxf(mx.y, s.y);
        mx.z = fmaxf(mx.z, s.z); mx.w = fmaxf(mx.w, s.w);
    }
    #pragma unroll
    for (int o=16;o>0;o>>=1){
        mx.x = fmaxf(mx.x, __shfl_down_sync(0xffffffffu, mx.x, o));
        mx.y = fmaxf(mx.y, __shfl_down_sync(0xffffffffu, mx.y, o));
        mx.z = fmaxf(mx.z, __shfl_down_sync(0xffffffffu, mx.z, o));
        mx.w = fmaxf(mx.w, __shfl_down_sync(0xffffffffu, mx.w, o));
    }
    __shared__ float4 sM[2];
    __shared__ float4 sD[2];
    if (lane == 0) sM[w] = mx;
    __syncthreads();
    mx.x = fmaxf(sM[0].x, sM[1].x); mx.y = fmaxf(sM[0].y, sM[1].y);
    mx.z = fmaxf(sM[0].z, sM[1].z); mx.w = fmaxf(sM[0].w, sM[1].w);

    float4 dn = make_float4(0.f,0.f,0.f,0.f);
    for (int i=beg+t; i<end; i+=64){
        float4 s = SC[g_eidx[i]];
        dn.x += __expf(s.x-mx.x); dn.y += __expf(s.y-mx.y);
        dn.z += __expf(s.z-mx.z); dn.w += __expf(s.w-mx.w);
    }
    #pragma unroll
    for (int o=16;o>0;o>>=1){
        dn.x += __shfl_down_sync(0xffffffffu, dn.x, o);
        dn.y += __shfl_down_sync(0xffffffffu, dn.y, o);
        dn.z += __shfl_down_sync(0xffffffffu, dn.z, o);
        dn.w += __shfl_down_sync(0xffffffffu, dn.w, o);
    }
    if (lane == 0) sD[w] = dn;
    __syncthreads();
    dn.x = sD[0].x + sD[1].x; dn.y = sD[0].y + sD[1].y;
    dn.z = sD[0].z + sD[1].z; dn.w = sD[0].w + sD[1].w;

    const int q = t >> 4;
    const float mq = (q==0)?mx.x:(q==1)?mx.y:(q==2)?mx.z:mx.w;
    const float dq = (q==0)?dn.x:(q==1)?dn.y:(q==2)?dn.z:dn.w;
    const float rq = (end > beg) ? 1.0f/dq : 0.f;
    float4 acc = make_float4(0.f,0.f,0.f,0.f);
    for (int i=beg; i<end; i++){
        int e = g_eidx[i];
        float a = __expf(g_score[(size_t)e*4 + q] - mq) * rq;
        float4 hp = reinterpret_cast<const float4*>(g_hp)[src[e]*64 + t];
        acc.x += hp.x*a; acc.y += hp.y*a; acc.z += hp.z*a; acc.w += hp.w*a;
    }

    __shared__ float sAcc[256];
    reinterpret_cast<float4*>(sAcc)[t] = acc;
    __syncthreads();
    float v = 0.25f*(sAcc[t] + sAcc[t+64] + sAcc[t+128] + sAcc[t+192]);
    float s1 = v, s2 = v*v;
    #pragma unroll
    for (int o=16;o>0;o>>=1){
        s1 += __shfl_down_sync(0xffffffffu, s1, o);
        s2 += __shfl_down_sync(0xffffffffu, s2, o);
    }
    __shared__ float sS[4];
    if (lane == 0){ sS[w] = s1; sS[2+w] = s2; }
    __syncthreads();
    float m   = (sS[0]+sS[1]) * 0.015625f;
    float var = (sS[2]+sS[3]) * 0.015625f - m*m;
    float o = (v - m) * rsqrtf(var + 1e-5f);
    o = o > 0.f ? o : expm1f(o);
    g_h[n*64 + t] = o;
    __nv_bfloat16 hi = __float2bfloat16(o);
    g_hb[(size_t)n*128 + t]      = hi;
    g_hb[(size_t)n*128 + 64 + t] = __float2bfloat16(o - __bfloat162float(hi));
}

// ---------------- host ----------------
extern "C" void kernel_launch(void* const* d_in, const int* in_sizes, int n_in,
                              void* d_out, int out_size){
    (void)in_sizes; (void)n_in; (void)out_size;
    const float* x      = (const float*)d_in[0];
    const float* efeat  = (const float*)d_in[1];
    const int*   src    = (const int*)  d_in[2];
    const int*   dst    = (const int*)  d_in[3];
    const float* Wn0    = (const float*)d_in[4];
    const float* bn0    = (const float*)d_in[5];
    const float* We0    = (const float*)d_in[6];
    const float* be0    = (const float*)d_in[7];
    const float* Wnode  = (const float*)d_in[8];
    const float* bnode  = (const float*)d_in[9];
    const float* Wni    = (const float*)d_in[10];
    const float* Wnj    = (const float*)d_in[11];
    const float* Wfij   = (const float*)d_in[12];
    const float* attn   = (const float*)d_in[13];
    const float* bias_e = (const float*)d_in[14];
    const float* Wf     = (const float*)d_in[15];
    const float* bf     = (const float*)d_in[16];

    float *p_ni, *p_nj, *p_hp;
    __nv_bfloat16 *p_hb, *p_wb;
    int* p_cur;
    cudaGetSymbolAddress((void**)&p_ni, g_ni);
    cudaGetSymbolAddress((void**)&p_nj, g_nj);
    cudaGetSymbolAddress((void**)&p_hp, g_hp);
    cudaGetSymbolAddress((void**)&p_hb, g_hb);
    cudaGetSymbolAddress((void**)&p_wb, g_wbuf);
    cudaGetSymbolAddress((void**)&p_cur, g_cur);

    cudaFuncSetAttribute(mma_gemm,  cudaFuncAttributeMaxDynamicSharedMemorySize, MMA_SMEM);
    cudaFuncSetAttribute(edge_gemm, cudaFuncAttributeMaxDynamicSharedMemorySize, MMA_SMEM);

    // kernel launch order arranged so index 3 (profiled) = edge_gemm
    sg_init<<<dim3(8192, 2), 256>>>(x, Wn0, bn0, efeat, We0, be0);        // 0
    k_wconv_all<<<dim3(192, 8), 256>>>(Wni, Wnj, Wnode, Wfij);            // 1
    // layer 0 GEMMs
    mma_gemm<<<dim3(157, 6), 256, MMA_SMEM>>>(
        p_hb, p_wb, bnode, p_ni, p_nj, p_hp, NN);                         // 2
    edge_gemm<<<dim3(1563, 2), 256, MMA_SMEM>>>(
        p_wb + (size_t)3*49152, src, dst, bias_e, attn);                  // 3  <-- profiled
    // CSR (needed by aggregate only)
    cudaMemsetAsync(p_cur, 0, NN*sizeof(int));
    k_count<<<(NE+255)/256, 256>>>(dst);                                  // 4
    k_scan<<<1, 1024>>>();                                                // 5
    k_scatter<<<(NE+255)/256, 256>>>(dst);                                // 6
    edge_b<<<(NE+3)/4, 256>>>();                                          // 7
    aggregate<<<NN, 64>>>(src);                                           // 8

    // layer 1
    mma_gemm<<<dim3(157, 6), 256, MMA_SMEM>>>(
        p_hb, p_wb + (size_t)4*49152, bnode + 256, p_ni, p_nj, p_hp, NN);
    edge_gemm<<<dim3(1563, 2), 256, MMA_SMEM>>>(
        p_wb + (size_t)7*49152, src, dst, bias_e + 256, attn + 256);
    edge_b<<<(NE+3)/4, 256>>>();
    aggregate<<<NN, 64>>>(src);

    sg_final<<<5000, 256>>>(Wf, bf, (float*)d_out);
}

// round 8
// speedup vs baseline: 1.3110x; 1.1899x over previous
#include <cuda_runtime.h>
#include <cuda_bf16.h>
#include <math.h>
#include <stdint.h>

#define NN 20000
#define NE 200000

// ---------------- scratch ----------------
__device__ __align__(16) float g_h[NN*64];
__device__ __align__(16) float g_ni[NN*256];
__device__ __align__(16) float g_nj[NN*256];
__device__ __align__(16) float g_hp[NN*256];
__device__ __align__(16) float g_score[NE*4];
__device__ int g_rowptr[NN+1];
__device__ int g_cur[NN];
__device__ int g_eidx[NE];
__device__ __align__(16) __nv_bfloat16 g_hb[NN*128];
__device__ __align__(16) __nv_bfloat16 g_fb[NE*128];
__device__ __align__(16) __nv_bfloat16 g_wbuf[8*49152];

// ---------------- helpers ----------------
__device__ __forceinline__ uint32_t smem_u32(const void* p){
    uint32_t a;
    asm("{ .reg .u64 t; cvta.to.shared.u64 t, %1; cvt.u32.u64 %0, t; }" : "=r"(a) : "l"(p));
    return a;
}
__device__ __forceinline__ void ldsm4(uint32_t& r0, uint32_t& r1, uint32_t& r2, uint32_t& r3, uint32_t a){
    asm volatile("ldmatrix.sync.aligned.m8n8.x4.shared.b16 {%0,%1,%2,%3}, [%4];"
        : "=r"(r0), "=r"(r1), "=r"(r2), "=r"(r3) : "r"(a));
}
#define MMA16816(d, a0,a1,a2,a3, b0,b1) \
    asm volatile("mma.sync.aligned.m16n8k16.row.col.f32.bf16.bf16.f32 " \
        "{%0,%1,%2,%3}, {%4,%5,%6,%7}, {%8,%9}, {%0,%1,%2,%3};" \
        : "+f"((d)[0]), "+f"((d)[1]), "+f"((d)[2]), "+f"((d)[3]) \
        : "r"(a0), "r"(a1), "r"(a2), "r"(a3), "r"(b0), "r"(b1))
__device__ __forceinline__ float lky(float x){ return x > 0.f ? x : 0.01f*x; }

// ---------------- CSR build ----------------
__global__ void k_count(const int* __restrict__ dst){
    int e = blockIdx.x*blockDim.x + threadIdx.x;
    if (e < NE) atomicAdd(&g_cur[dst[e]], 1);
}
__global__ __launch_bounds__(1024) void k_scan(){
    __shared__ int sPart[1024];
    const int t = threadIdx.x;
    const int beg = t*20;
    const int end = (beg+20 < NN) ? beg+20 : NN;
    int s = 0;
    for (int i=beg; i<end; i++) s += g_cur[i];
    sPart[t] = s;
    __syncthreads();
    for (int o=1; o<1024; o<<=1){
        int v = (t >= o) ? sPart[t-o] : 0;
        __syncthreads();
        sPart[t] += v;
        __syncthreads();
    }
    int run = (t==0) ? 0 : sPart[t-1];
    for (int i=beg; i<end; i++){
        int c = g_cur[i];
        g_rowptr[i] = run;
        g_cur[i]    = run;
        run += c;
    }
    if (t == 0) g_rowptr[NN] = NE;
}
__global__ void k_scatter(const int* __restrict__ dst){
    int e = blockIdx.x*blockDim.x + threadIdx.x;
    if (e < NE){
        int p = atomicAdd(&g_cur[dst[e]], 1);
        g_eidx[p] = e;
    }
}

// ---------------- W' images ----------------
__global__ __launch_bounds__(256) void k_wconv_all(
    const float* __restrict__ Wni, const float* __restrict__ Wnj,
    const float* __restrict__ Wnode, const float* __restrict__ Wfij){
    int idx = blockIdx.x*256 + threadIdx.x;
    if (idx >= 49152) return;
    int m = blockIdx.y;
    int l = m >> 2, which = m & 3;
    const float* W = (which==0?Wni: which==1?Wnj: which==2?Wnode: Wfij) + l*16384;
    int n = idx / 192, kk = idx % 192;
    int ks = kk & 63;
    float v = W[ks*256 + n];
    __nv_bfloat16 h = __float2bfloat16(v);
    if (kk >= 128) h = __float2bfloat16(v - __bfloat162float(h));
    g_wbuf[(size_t)m*49152 + n*192 + kk] = h;
}

// ---------------- node GEMM (ldmatrix fragments) ----------------
#define MSTR 200
#define MMA_SMEM (2*128*MSTR*2)

__global__ __launch_bounds__(256) void mma_gemm(
    const __nv_bfloat16* __restrict__ ab, const __nv_bfloat16* __restrict__ wimg0,
    const float* __restrict__ bias2,
    float* __restrict__ o0, float* __restrict__ o1, float* __restrict__ o2,
    int rows){
    extern __shared__ __nv_bfloat16 sm[];
    __nv_bfloat16* sA = sm;
    __nv_bfloat16* sW = sm + 128*MSTR;
    const int tid = threadIdx.x;
    const int y = blockIdx.y;
    const int mat = y >> 1;
    const int ch  = y & 1;
    const __nv_bfloat16* wimg = wimg0 + (size_t)mat*49152;
    float* out = (mat==0) ? o0 : (mat==1) ? o1 : o2;
    const float* bias = (mat==2) ? bias2 : nullptr;
    const int row0 = blockIdx.x*128;
    const int cb   = ch*128;

    #pragma unroll
    for (int it=0; it<8; it++){
        int idx = it*256 + tid;
        int r = idx >> 4, c8 = (idx & 15)*8;
        uint4 v = make_uint4(0u,0u,0u,0u);
        if (row0 + r < rows) v = *reinterpret_cast<const uint4*>(ab + (size_t)(row0+r)*128 + c8);
        *reinterpret_cast<uint4*>(sA + r*MSTR + c8) = v;
    }
    #pragma unroll
    for (int it=0; it<4; it++){
        int idx = it*256 + tid;
        int r = idx >> 3, c8 = (idx & 7)*8;
        uint4 v = make_uint4(0u,0u,0u,0u);
        if (row0 + r < rows) v = *reinterpret_cast<const uint4*>(ab + (size_t)(row0+r)*128 + c8);
        *reinterpret_cast<uint4*>(sA + r*MSTR + 128 + c8) = v;
    }
    #pragma unroll
    for (int it=0; it<12; it++){
        int idx = it*256 + tid;
        int n = idx / 24, c8 = (idx % 24)*8;
        uint4 v = *reinterpret_cast<const uint4*>(wimg + (size_t)(cb+n)*192 + c8);
        *reinterpret_cast<uint4*>(sW + n*MSTR + c8) = v;
    }
    __syncthreads();

    const int wid = tid >> 5, lane = tid & 31;
    const int wrow = wid & 1, wcol = wid >> 1;
    const int lr = lane >> 2, lk2 = (lane & 3)*2;
    const uint32_t sAu = smem_u32(sA), sWu = smem_u32(sW);
    const uint32_t arow = (uint32_t)((wrow*64 + (lane & 15))*MSTR + ((lane >> 4) << 3));
    const uint32_t brow = (uint32_t)((wcol*32 + (lane & 7) + ((lane >> 4) << 3))*MSTR + (lane & 8));

    float acc[4][4][4];
    #pragma unroll
    for (int mi=0;mi<4;mi++)
        #pragma unroll
        for (int ni=0;ni<4;ni++)
            #pragma unroll
            for (int q=0;q<4;q++) acc[mi][ni][q] = 0.f;

    #pragma unroll
    for (int ks=0; ks<12; ks++){
        const int k = ks*16;
        uint32_t a[4][4];
        #pragma unroll
        for (int mi=0;mi<4;mi++)
            ldsm4(a[mi][0], a[mi][1], a[mi][2], a[mi][3],
                  sAu + 2u*(arow + (uint32_t)(mi*16*MSTR + k)));
        #pragma unroll
        for (int pr=0; pr<2; pr++){
            uint32_t b0, b1, b2, b3;
            ldsm4(b0, b1, b2, b3, sWu + 2u*(brow + (uint32_t)(pr*16*MSTR + k)));
            #pragma unroll
            for (int mi=0;mi<4;mi++){
                MMA16816(acc[mi][pr*2],   a[mi][0], a[mi][1], a[mi][2], a[mi][3], b0, b1);
                MMA16816(acc[mi][pr*2+1], a[mi][0], a[mi][1], a[mi][2], a[mi][3], b2, b3);
            }
        }
    }

    #pragma unroll
    for (int mi=0;mi<4;mi++){
        #pragma unroll
        for (int ni=0;ni<4;ni++){
            int r = row0 + wrow*64 + mi*16 + lr;
            int c = cb + wcol*32 + ni*8 + lk2;
            float bx = 0.f, by = 0.f;
            if (bias){ bx = bias[c]; by = bias[c+1]; }
            if (r < rows){
                float2 v = make_float2(acc[mi][ni][0] + bx, acc[mi][ni][1] + by);
                *reinterpret_cast<float2*>(out + (size_t)r*256 + c) = v;
            }
            if (r + 8 < rows){
                float2 v = make_float2(acc[mi][ni][2] + bx, acc[mi][ni][3] + by);
                *reinterpret_cast<float2*>(out + (size_t)(r+8)*256 + c) = v;
            }
        }
    }
}

// ---------------- edge GEMM v2: one pass, full 256 cols, fused epilogue ----------------
#define ASTR 104
#define WSTR 104
#define FOS  260
#define EG_SMEM 133632   // sFo 128*260*4 = 133120 (covers sA 26624 + sW 53248 mainloop)

__global__ __launch_bounds__(512) void edge_gemm(
    const __nv_bfloat16* __restrict__ wimg,
    const int* __restrict__ src, const int* __restrict__ dst,
    const float* __restrict__ bias_e, const float* __restrict__ attn){
    extern __shared__ __nv_bfloat16 sm[];
    __nv_bfloat16* sA = sm;                   // [128][ASTR], 96 k used
    __nv_bfloat16* sW = sm + 128*ASTR;        // [256][WSTR], 96 k used
    const int tid = threadIdx.x;
    const int e0 = blockIdx.x*128;
    const int wid = tid >> 5, lane = tid & 31;
    const int wrow = wid & 3, wcol = wid >> 2;   // warp tile m32 x n64
    const int lr = lane >> 2, lk2 = (lane & 3)*2;
    const uint32_t sAu = smem_u32(sA), sWu = smem_u32(sW);
    const uint32_t arow = (uint32_t)((wrow*32 + (lane & 15))*ASTR + ((lane >> 4) << 3));
    const uint32_t brow = (uint32_t)((wcol*64 + (lane & 7) + ((lane >> 4) << 3))*WSTR + (lane & 8));

    float acc[2][8][4];
    #pragma unroll
    for (int mi=0;mi<2;mi++)
        #pragma unroll
        for (int n8=0;n8<8;n8++)
            #pragma unroll
            for (int q=0;q<4;q++) acc[mi][n8][q] = 0.f;

    #pragma unroll 1
    for (int ck=0; ck<2; ck++){
        __syncthreads();
        // A: 128 rows x 96 cols; chunk1 cols = fb[96..127] then fb[0..63]
        #pragma unroll
        for (int it=0; it<3; it++){
            int idx = it*512 + tid;            // 1536 uint4
            int r = idx / 12, c8 = idx - r*12;
            int fc8 = (ck == 0) ? c8 : ((c8 < 4) ? 12 + c8 : c8 - 4);
            uint4 v = make_uint4(0u,0u,0u,0u);
            if (e0 + r < NE) v = *reinterpret_cast<const uint4*>(g_fb + (size_t)(e0+r)*128 + fc8*8);
            *reinterpret_cast<uint4*>(sA + r*ASTR + c8*8) = v;
        }
        // W: 256 rows x 96 cols of this chunk
        #pragma unroll
        for (int it=0; it<6; it++){
            int idx = it*512 + tid;            // 3072 uint4
            int n = idx / 12, c8 = idx - n*12;
            uint4 v = *reinterpret_cast<const uint4*>(wimg + (size_t)n*192 + ck*96 + c8*8);
            *reinterpret_cast<uint4*>(sW + n*WSTR + c8*8) = v;
        }
        __syncthreads();

        #pragma unroll
        for (int ks=0; ks<6; ks++){
            const int k = ks*16;
            uint32_t a[2][4];
            #pragma unroll
            for (int mi=0;mi<2;mi++)
                ldsm4(a[mi][0], a[mi][1], a[mi][2], a[mi][3],
                      sAu + 2u*(arow + (uint32_t)(mi*16*ASTR + k)));
            #pragma unroll
            for (int nb=0; nb<4; nb++){
                uint32_t b0, b1, b2, b3;
                ldsm4(b0, b1, b2, b3, sWu + 2u*(brow + (uint32_t)(nb*16*WSTR + k)));
                #pragma unroll
                for (int mi=0;mi<2;mi++){
                    MMA16816(acc[mi][nb*2],   a[mi][0], a[mi][1], a[mi][2], a[mi][3], b0, b1);
                    MMA16816(acc[mi][nb*2+1], a[mi][0], a[mi][1], a[mi][2], a[mi][3], b2, b3);
                }
            }
        }
    }
    __syncthreads();

    // spill fo (pre-bias) into sFo [128][FOS]
    float* sFo = reinterpret_cast<float*>(sm);
    #pragma unroll
    for (int mi=0;mi<2;mi++){
        int rl = wrow*32 + mi*16 + lr;
        #pragma unroll
        for (int n8=0;n8<8;n8++){
            int c = wcol*64 + n8*8 + lk2;
            sFo[rl*FOS + c]         = acc[mi][n8][0];
            sFo[rl*FOS + c + 1]     = acc[mi][n8][1];
            sFo[(rl+8)*FOS + c]     = acc[mi][n8][2];
            sFo[(rl+8)*FOS + c + 1] = acc[mi][n8][3];
        }
    }
    __syncthreads();

    // epilogue: warp-per-edge, 8 edges per warp, one-ahead gather pipeline
    const int c1 = lane*4, c2 = 128 + lane*4;
    const float4 be1 = *reinterpret_cast<const float4*>(bias_e + c1);
    const float4 be2 = *reinterpret_cast<const float4*>(bias_e + c2);
    const float4 at1 = *reinterpret_cast<const float4*>(attn + c1);
    const float4 at2 = *reinterpret_cast<const float4*>(attn + c2);

    float4 n1c, n2c, j1c, j2c;
    {
        int e = e0 + wid*8;
        int s = 0, d = 0;
        if (e < NE){ s = src[e]; d = dst[e]; }
        n1c = *reinterpret_cast<const float4*>(g_ni + (size_t)s*256 + c1);
        n2c = *reinterpret_cast<const float4*>(g_ni + (size_t)s*256 + c2);
        j1c = *reinterpret_cast<const float4*>(g_nj + (size_t)d*256 + c1);
        j2c = *reinterpret_cast<const float4*>(g_nj + (size_t)d*256 + c2);
    }

    #pragma unroll 1
    for (int it=0; it<8; it++){
        const int el = wid*8 + it;
        const int e  = e0 + el;
        if (e >= NE) break;
        float4 n1 = n1c, n2 = n2c, j1 = j1c, j2 = j2c;
        if (it < 7){
            int e2 = e + 1;
            int s2 = 0, d2 = 0;
            if (e2 < NE){ s2 = src[e2]; d2 = dst[e2]; }
            n1c = *reinterpret_cast<const float4*>(g_ni + (size_t)s2*256 + c1);
            n2c = *reinterpret_cast<const float4*>(g_ni + (size_t)s2*256 + c2);
            j1c = *reinterpret_cast<const float4*>(g_nj + (size_t)d2*256 + c1);
            j2c = *reinterpret_cast<const float4*>(g_nj + (size_t)d2*256 + c2);
        }
        float4 f1 = *reinterpret_cast<const float4*>(sFo + el*FOS + c1);
        float4 f2 = *reinterpret_cast<const float4*>(sFo + el*FOS + c2);
        f1.x += be1.x + n1.x + j1.x; f1.y += be1.y + n1.y + j1.y;
        f1.z += be1.z + n1.z + j1.z; f1.w += be1.w + n1.w + j1.w;
        f2.x += be2.x + n2.x + j2.x; f2.y += be2.y + n2.y + j2.y;
        f2.z += be2.z + n2.z + j2.z; f2.w += be2.w + n2.w + j2.w;

        // scores: p1 = heads 0/1 (lanes 0-15 / 16-31), p2 = heads 2/3
        float p1 = lky(f1.x)*at1.x + lky(f1.y)*at1.y + lky(f1.z)*at1.z + lky(f1.w)*at1.w;
        float p2 = lky(f2.x)*at2.x + lky(f2.y)*at2.y + lky(f2.z)*at2.z + lky(f2.w)*at2.w;
        #pragma unroll
        for (int o=8;o>0;o>>=1){
            p1 += __shfl_xor_sync(0xffffffffu, p1, o);
            p2 += __shfl_xor_sync(0xffffffffu, p2, o);
        }
        if (lane == 0){
            g_score[(size_t)e*4 + 0] = p1;
            g_score[(size_t)e*4 + 2] = p2;
        } else if (lane == 16){
            g_score[(size_t)e*4 + 1] = p1;
            g_score[(size_t)e*4 + 3] = p2;
        }

        // head mean over 4 heads: lane pairs (L, L+16) hold same t = (lane&15)*4
        float4 hm;
        hm.x = f1.x + f2.x; hm.y = f1.y + f2.y; hm.z = f1.z + f2.z; hm.w = f1.w + f2.w;
        hm.x = 0.25f*(hm.x + __shfl_xor_sync(0xffffffffu, hm.x, 16));
        hm.y = 0.25f*(hm.y + __shfl_xor_sync(0xffffffffu, hm.y, 16));
        hm.z = 0.25f*(hm.z + __shfl_xor_sync(0xffffffffu, hm.z, 16));
        hm.w = 0.25f*(hm.w + __shfl_xor_sync(0xffffffffu, hm.w, 16));
        float s1 = hm.x + hm.y + hm.z + hm.w;
        float s2 = hm.x*hm.x + hm.y*hm.y + hm.z*hm.z + hm.w*hm.w;
        #pragma unroll
        for (int o=8;o>0;o>>=1){
            s1 += __shfl_xor_sync(0xffffffffu, s1, o);
            s2 += __shfl_xor_sync(0xffffffffu, s2, o);
        }
        float m   = s1 * 0.015625f;
        float var = s2 * 0.015625f - m*m;
        float inv = rsqrtf(var + 1e-5f);
        if (lane < 16){
            float4 o4;
            o4.x = (hm.x - m)*inv; o4.x = o4.x > 0.f ? o4.x : expm1f(o4.x);
            o4.y = (hm.y - m)*inv; o4.y = o4.y > 0.f ? o4.y : expm1f(o4.y);
            o4.z = (hm.z - m)*inv; o4.z = o4.z > 0.f ? o4.z : expm1f(o4.z);
            o4.w = (hm.w - m)*inv; o4.w = o4.w > 0.f ? o4.w : expm1f(o4.w);
            __nv_bfloat16 h0 = __float2bfloat16(o4.x), h1 = __float2bfloat16(o4.y);
            __nv_bfloat16 h2 = __float2bfloat16(o4.z), h3 = __float2bfloat16(o4.w);
            __nv_bfloat16 l0 = __float2bfloat16(o4.x - __bfloat162float(h0));
            __nv_bfloat16 l1 = __float2bfloat16(o4.y - __bfloat162float(h1));
            __nv_bfloat16 l2 = __float2bfloat16(o4.z - __bfloat162float(h2));
            __nv_bfloat16 l3 = __float2bfloat16(o4.w - __bfloat162float(h3));
            int t = c1;   // (lane&15)*4 for lanes 0-15
            __nv_bfloat162* dh = reinterpret_cast<__nv_bfloat162*>(g_fb + (size_t)e*128 + t);
            dh[0] = __nv_bfloat162(h0, h1);
            dh[1] = __nv_bfloat162(h2, h3);
            __nv_bfloat162* dl = reinterpret_cast<__nv_bfloat162*>(g_fb + (size_t)e*128 + 64 + t);
            dl[0] = __nv_bfloat162(l0, l1);
            dl[1] = __nv_bfloat162(l2, l3);
        }
    }
}

// ---------------- small GEMMs ----------------
__global__ __launch_bounds__(256) void sg_init(
    const float* __restrict__ A0, const float* __restrict__ W0, const float* __restrict__ b0,
    const float* __restrict__ A1, const float* __restrict__ W1, const float* __restrict__ b1){
    const int y = blockIdx.y;
    const float* A = y ? A1 : A0;
    const float* W = y ? W1 : W0;
    const float* bias = y ? b1 : b0;
    __nv_bfloat16* out2 = y ? g_fb : g_hb;
    const int rows = y ? NE : NN;
    const int K    = y ? 15 : 65;
    __shared__ float sW[65*64];
    __shared__ float sA[4*65];
    for (int i=threadIdx.x; i<K*64; i+=256) sW[i] = W[i];
    __syncthreads();
    const int col = threadIdx.x & 63;
    const int rl  = threadIdx.x >> 6;
    const float b = bias[col];
    for (int base = blockIdx.x*4; base < rows; base += gridDim.x*4){
        for (int i=threadIdx.x; i<4*K; i+=256){
            int r = i / K, k = i - r*K;
            sA[i] = (base + r < rows) ? A[(size_t)(base+r)*K + k] : 0.f;
        }
        __syncthreads();
        const int row = base + rl;
        if (row < rows){
            float acc = b;
            for (int k=0;k<K;k++) acc += sA[rl*K + k]*sW[k*64 + col];
            __nv_bfloat16 h = __float2bfloat16(acc);
            out2[(size_t)row*128 + col]      = h;
            out2[(size_t)row*128 + 64 + col] = __float2bfloat16(acc - __bfloat162float(h));
        }
        __syncthreads();
    }
}

__global__ __launch_bounds__(256) void sg_final(
    const float* __restrict__ W, const float* __restrict__ bias, float* __restrict__ out){
    __shared__ float sW[64*64];
    __shared__ float sA[4*64];
    for (int i=threadIdx.x; i<64*64; i+=256) sW[i] = W[i];
    __syncthreads();
    const int col = threadIdx.x & 63;
    const int rl  = threadIdx.x >> 6;
    const float b = bias[col];
    for (int base = blockIdx.x*4; base < NN; base += gridDim.x*4){
        for (int i=threadIdx.x; i<4*64; i+=256){
            int r = i >> 6, k = i & 63;
            sA[i] = (base + r < NN) ? g_h[(base+r)*64 + k] : 0.f;
        }
        __syncthreads();
        const int row = base + rl;
        if (row < NN){
            float acc = b;
            for (int k=0;k<64;k++) acc += sA[rl*64 + k]*sW[k*64 + col];
            out[row*64 + col] = acc;
        }
        __syncthreads();
    }
}

// ---------------- fused softmax + aggregate + mean-heads + inorm + elu ----------------
__global__ __launch_bounds__(64) void aggregate(const int* __restrict__ src){
    const int n = blockIdx.x, t = threadIdx.x;
    const int w = t >> 5, lane = t & 31;
    const int beg = g_rowptr[n], end = g_rowptr[n+1];
    const float4* SC = reinterpret_cast<const float4*>(g_score);

    float4 mx = make_float4(-3.4e38f,-3.4e38f,-3.4e38f,-3.4e38f);
    for (int i=beg+t; i<end; i+=64){
        float4 s = SC[g_eidx[i]];
        mx.x = fmaxf(mx.x, s.x); mx.y = fmaxf(mx.y, s.y);
        mx.z = fmaxf(mx.z, s.z); mx.w = fmaxf(mx.w, s.w);
    }
    #pragma unroll
    for (int o=16;o>0;o>>=1){
        mx.x = fmaxf(mx.x, __shfl_down_sync(0xffffffffu, mx.x, o));
        mx.y = fmaxf(mx.y, __shfl_down_sync(0xffffffffu, mx.y, o));
        mx.z = fmaxf(mx.z, __shfl_down_sync(0xffffffffu, mx.z, o));
        mx.w = fmaxf(mx.w, __shfl_down_sync(0xffffffffu, mx.w, o));
    }
    __shared__ float4 sM[2];
    __shared__ float4 sD[2];
    if (lane == 0) sM[w] = mx;
    __syncthreads();
    mx.x = fmaxf(sM[0].x, sM[1].x); mx.y = fmaxf(sM[0].y, sM[1].y);
    mx.z = fmaxf(sM[0].z, sM[1].z); mx.w = fmaxf(sM[0].w, sM[1].w);

    float4 dn = make_float4(0.f,0.f,0.f,0.f);
    for (int i=beg+t; i<end; i+=64){
        float4 s = SC[g_eidx[i]];
        dn.x += __expf(s.x-mx.x); dn.y += __expf(s.y-mx.y);
        dn.z += __expf(s.z-mx.z); dn.w += __expf(s.w-mx.w);
    }
    #pragma unroll
    for (int o=16;o>0;o>>=1){
        dn.x += __shfl_down_sync(0xffffffffu, dn.x, o);
        dn.y += __shfl_down_sync(0xffffffffu, dn.y, o);
        dn.z += __shfl_down_sync(0xffffffffu, dn.z, o);
        dn.w += __shfl_down_sync(0xffffffffu, dn.w, o);
    }
    if (lane == 0) sD[w] = dn;
    __syncthreads();
    dn.x = sD[0].x + sD[1].x; dn.y = sD[0].y + sD[1].y;
    dn.z = sD[0].z + sD[1].z; dn.w = sD[0].w + sD[1].w;

    const int q = t >> 4;
    const float mq = (q==0)?mx.x:(q==1)?mx.y:(q==2)?mx.z:mx.w;
    const float dq = (q==0)?dn.x:(q==1)?dn.y:(q==2)?dn.z:dn.w;
    const float rq = (end > beg) ? 1.0f/dq : 0.f;
    float4 acc = make_float4(0.f,0.f,0.f,0.f);
    for (int i=beg; i<end; i++){
        int e = g_eidx[i];
        float a = __expf(g_score[(size_t)e*4 + q] - mq) * rq;
        float4 hp = reinterpret_cast<const float4*>(g_hp)[src[e]*64 + t];
        acc.x += hp.x*a; acc.y += hp.y*a; acc.z += hp.z*a; acc.w += hp.w*a;
    }

    __shared__ float sAcc[256];
    reinterpret_cast<float4*>(sAcc)[t] = acc;
    __syncthreads();
    float v = 0.25f*(sAcc[t] + sAcc[t+64] + sAcc[t+128] + sAcc[t+192]);
    float s1 = v, s2 = v*v;
    #pragma unroll
    for (int o=16;o>0;o>>=1){
        s1 += __shfl_down_sync(0xffffffffu, s1, o);
        s2 += __shfl_down_sync(0xffffffffu, s2, o);
    }
    __shared__ float sS[4];
    if (lane == 0){ sS[w] = s1; sS[2+w] = s2; }
    __syncthreads();
    float m   = (sS[0]+sS[1]) * 0.015625f;
    float var = (sS[2]+sS[3]) * 0.015625f - m*m;
    float o = (v - m) * rsqrtf(var + 1e-5f);
    o = o > 0.f ? o : expm1f(o);
    g_h[n*64 + t] = o;
    __nv_bfloat16 hi = __float2bfloat16(o);
    g_hb[(size_t)n*128 + t]      = hi;
    g_hb[(size_t)n*128 + 64 + t] = __float2bfloat16(o - __bfloat162float(hi));
}

// ---------------- host ----------------
extern "C" void kernel_launch(void* const* d_in, const int* in_sizes, int n_in,
                              void* d_out, int out_size){
    (void)in_sizes; (void)n_in; (void)out_size;
    const float* x      = (const float*)d_in[0];
    const float* efeat  = (const float*)d_in[1];
    const int*   src    = (const int*)  d_in[2];
    const int*   dst    = (const int*)  d_in[3];
    const float* Wn0    = (const float*)d_in[4];
    const float* bn0    = (const float*)d_in[5];
    const float* We0    = (const float*)d_in[6];
    const float* be0    = (const float*)d_in[7];
    const float* Wnode  = (const float*)d_in[8];
    const float* bnode  = (const float*)d_in[9];
    const float* Wni    = (const float*)d_in[10];
    const float* Wnj    = (const float*)d_in[11];
    const float* Wfij   = (const float*)d_in[12];
    const float* attn   = (const float*)d_in[13];
    const float* bias_e = (const float*)d_in[14];
    const float* Wf     = (const float*)d_in[15];
    const float* bf     = (const float*)d_in[16];

    float *p_ni, *p_nj, *p_hp;
    __nv_bfloat16 *p_hb, *p_wb;
    int* p_cur;
    cudaGetSymbolAddress((void**)&p_ni, g_ni);
    cudaGetSymbolAddress((void**)&p_nj, g_nj);
    cudaGetSymbolAddress((void**)&p_hp, g_hp);
    cudaGetSymbolAddress((void**)&p_hb, g_hb);
    cudaGetSymbolAddress((void**)&p_wb, g_wbuf);
    cudaGetSymbolAddress((void**)&p_cur, g_cur);

    cudaFuncSetAttribute(mma_gemm,  cudaFuncAttributeMaxDynamicSharedMemorySize, MMA_SMEM);
    cudaFuncSetAttribute(edge_gemm, cudaFuncAttributeMaxDynamicSharedMemorySize, EG_SMEM);

    sg_init<<<dim3(8192, 2), 256>>>(x, Wn0, bn0, efeat, We0, be0);        // 0
    k_wconv_all<<<dim3(192, 8), 256>>>(Wni, Wnj, Wnode, Wfij);            // 1
    mma_gemm<<<dim3(157, 6), 256, MMA_SMEM>>>(
        p_hb, p_wb, bnode, p_ni, p_nj, p_hp, NN);                         // 2
    edge_gemm<<<1563, 512, EG_SMEM>>>(
        p_wb + (size_t)3*49152, src, dst, bias_e, attn);                  // 3  <-- profiled
    cudaMemsetAsync(p_cur, 0, NN*sizeof(int));
    k_count<<<(NE+255)/256, 256>>>(dst);
    k_scan<<<1, 1024>>>();
    k_scatter<<<(NE+255)/256, 256>>>(dst);
    aggregate<<<NN, 64>>>(src);

    mma_gemm<<<dim3(157, 6), 256, MMA_SMEM>>>(
        p_hb, p_wb + (size_t)4*49152, bnode + 256, p_ni, p_nj, p_hp, NN);
    edge_gemm<<<1563, 512, EG_SMEM>>>(
        p_wb + (size_t)7*49152, src, dst, bias_e + 256, attn + 256);
    aggregate<<<NN, 64>>>(src);

    sg_final<<<5000, 256>>>(Wf, bf, (float*)d_out);
}